// round 12
// baseline (speedup 1.0000x reference)
#include <cuda_runtime.h>
#include <math.h>

#define BB   32
#define TXT  256
#define MELT 400
#define ENC  512
#define NMEL 80
#define PRE  256
#define RNN  1024
#define AD   128
#define NBLK 128
#define NEGV (-1e9f)

#define GATE_OFF  (BB*NMEL*MELT)
#define ALIGN_OFF (GATE_OFF + BB*MELT)

// ---------------- device-global scratch (allocation-free) ----------------
__device__ float g_x1  [(size_t)MELT*BB*PRE];    // [u=t*32+b][p]
__device__ float g_xpre[(size_t)MELT*PRE*BB];    // [t][k][b]
__device__ float g_pm  [(size_t)BB*TXT*AD];      // [b][tt][a]
__device__ float g_loc [(size_t)BB*TXT*AD];      // [b][tt][a]
__device__ float g_qWt [(size_t)RNN*AD];         // [k][a]
__device__ float g_ah  [2][RNN*BB];              // [k][b]
__device__ float g_ac  [RNN*BB];
__device__ float g_dh  [2][RNN*BB];
__device__ float g_dc  [RNN*BB];
__device__ float g_aw  [BB*TXT];
__device__ float g_awc [BB*TXT];
__device__ float g_ctx [ENC*BB];                 // [k][b]
__device__ float g_dhh [(size_t)MELT*RNN*BB];    // [t][k][b]
__device__ float g_ctxh[(size_t)MELT*ENC*BB];    // [t][k][b]
__device__ unsigned g_barc;
__device__ unsigned g_barg;

__device__ __forceinline__ float sigm(float x) { return 1.0f/(1.0f+expf(-x)); }
__device__ __forceinline__ float tanha(float x) {
    float y; asm("tanh.approx.f32 %0, %1;" : "=f"(y) : "f"(x)); return y;
}

__device__ __forceinline__ void gbar() {
    __syncthreads();
    if (threadIdx.x == 0) {
        __threadfence();
        unsigned gen = *(volatile unsigned*)&g_barg;
        if (atomicAdd(&g_barc, 1u) == NBLK - 1u) {
            g_barc = 0u;
            __threadfence();
            *(volatile unsigned*)&g_barg = gen + 1u;
        } else {
            while (*(volatile unsigned*)&g_barg == gen) { __nanosleep(64); }
        }
        __threadfence();
    }
    __syncthreads();
}

// 32 rows x 32 batch tile GEMM; double-buffered staging; X layout [k][b], b-stride 32.
// thread: r = tid>>3 row, b0 = (tid&7)*4 batches. w_s: 2*1056, x_s: 2*1024 floats.
__device__ __forceinline__ void gemm32db(float4& acc,
    const float* const* rowp, int col0,
    const float* __restrict__ X, int K,
    float* w_s, float* x_s)
{
    const int tid = threadIdx.x;
    const int r = tid >> 3, b0 = (tid & 7) << 2;
    const int rr = tid >> 5, kk = tid & 31;
    const int nt = K >> 5;
    float wreg[4], xreg[4];
    #pragma unroll
    for (int i = 0; i < 4; i++) wreg[i] = rowp[rr + i*8][col0 + kk];
    #pragma unroll
    for (int i = 0; i < 4; i++) xreg[i] = __ldcg(X + tid + i*256);
    __syncthreads();                       // previous consumers of w_s/x_s done
    #pragma unroll
    for (int i = 0; i < 4; i++) w_s[kk*33 + rr + i*8] = wreg[i];
    #pragma unroll
    for (int i = 0; i < 4; i++) x_s[tid + i*256] = xreg[i];
    for (int kt = 0; kt < nt; kt++) {
        const int cur = kt & 1;
        if (kt + 1 < nt) {
            const int kc = col0 + (kt + 1)*32 + kk;
            const float* Xn = X + (size_t)(kt + 1)*1024;
            #pragma unroll
            for (int i = 0; i < 4; i++) wreg[i] = rowp[rr + i*8][kc];
            #pragma unroll
            for (int i = 0; i < 4; i++) xreg[i] = __ldcg(Xn + tid + i*256);
        }
        __syncthreads();                   // staged buffer visible
        const float* ws = w_s + cur*1056 + r;
        const float* xs = x_s + cur*1024 + b0;
        #pragma unroll
        for (int k2 = 0; k2 < 32; k2++) {
            float w = ws[k2*33];
            float4 xv = *reinterpret_cast<const float4*>(xs + k2*32);
            acc.x = fmaf(w, xv.x, acc.x);
            acc.y = fmaf(w, xv.y, acc.y);
            acc.z = fmaf(w, xv.z, acc.z);
            acc.w = fmaf(w, xv.w, acc.w);
        }
        if (kt + 1 < nt) {
            const int nb = (kt + 1) & 1;
            __syncthreads();               // all warps done consuming buffer nb
            float* wsn = w_s + nb*1056;
            float* xsn = x_s + nb*1024;
            #pragma unroll
            for (int i = 0; i < 4; i++) wsn[kk*33 + rr + i*8] = wreg[i];
            #pragma unroll
            for (int i = 0; i < 4; i++) xsn[tid + i*256] = xreg[i];
        }
    }
}

// one 32-row gate tile (this block's 8 h-units x 4 gates) of an LSTM step
__device__ __forceinline__ void lstm_tile(
    const float* __restrict__ Wi, int wild, const float* __restrict__ Wh,
    const float* __restrict__ bias,
    const float* __restrict__ X1, int K1,
    const float* __restrict__ X2, int K2,
    const float* __restrict__ hprev, float* __restrict__ cst,
    float* __restrict__ hout, float* __restrict__ hist,
    float* w_s, float* x_s, const float** rowp)
{
    const int tid = threadIdx.x, blk = blockIdx.x;
    const int r = tid >> 3, b0 = (tid & 7) << 2;
    __syncthreads();
    if (tid < 32)
        rowp[tid] = Wi + (size_t)((tid >> 3)*RNN + blk*8 + (tid & 7)) * wild;
    __syncthreads();
    float bv = bias[(r >> 3)*RNN + blk*8 + (r & 7)];
    float4 acc = make_float4(bv, bv, bv, bv);
    gemm32db(acc, rowp, 0,  X1, K1, w_s, x_s);
    gemm32db(acc, rowp, K1, X2, K2, w_s, x_s);
    __syncthreads();
    if (tid < 32)
        rowp[tid] = Wh + (size_t)((tid >> 3)*RNN + blk*8 + (tid & 7)) * RNN;
    __syncthreads();
    gemm32db(acc, rowp, 0, hprev, RNN, w_s, x_s);
    __syncthreads();
    x_s[r*32 + b0 + 0] = acc.x; x_s[r*32 + b0 + 1] = acc.y;
    x_s[r*32 + b0 + 2] = acc.z; x_s[r*32 + b0 + 3] = acc.w;
    __syncthreads();
    {
        int j = tid >> 5, b = tid & 31, h = blk*8 + j;
        float iv = x_s[( 0 + j)*32 + b];
        float fv = x_s[( 8 + j)*32 + b];
        float gv = x_s[(16 + j)*32 + b];
        float ov = x_s[(24 + j)*32 + b];
        float c  = sigm(fv)*cst[h*32 + b] + sigm(iv)*tanhf(gv);
        float hn = sigm(ov)*tanhf(c);
        cst[h*32 + b] = c;
        hout[h*32 + b] = hn;
        if (hist) hist[h*32 + b] = hn;
    }
    __syncthreads();
}

__global__ __launch_bounds__(256, 1) void decoder_all(
    const float* __restrict__ memory, const float* __restrict__ din,
    const int* __restrict__ mlen,
    const float* __restrict__ preW1, const float* __restrict__ preW2,
    const float* __restrict__ aWi, const float* __restrict__ aWh,
    const float* __restrict__ aB,
    const float* __restrict__ convW, const float* __restrict__ denseW,
    const float* __restrict__ queryW, const float* __restrict__ memW,
    const float* __restrict__ vW,
    const float* __restrict__ dWi, const float* __restrict__ dWh,
    const float* __restrict__ dB,
    const float* __restrict__ projW, const float* __restrict__ projB,
    const float* __restrict__ gateW, const float* __restrict__ gateB,
    float* __restrict__ out)
{
    __shared__ __align__(16) float w_s[2112];
    __shared__ __align__(16) float x_s[2048];
    __shared__ __align__(16) float cw_s[1984];
    __shared__ __align__(16) float dW_s[4096];
    __shared__ const float* rowp[32];
    const int blk = blockIdx.x, tid = threadIdx.x;

    for (int i = tid; i < 1984; i += 256) cw_s[i] = convW[i];
    for (int i = tid; i < 4096; i += 256) dW_s[i] = denseW[i];

    // -------- prologue (one interval; per-unit work is block-local) --------
    {   // zero recurrent state: block blk covers h rows [blk*8, blk*8+8)
        int i = blk*256 + tid;
        g_ah[0][i] = 0.f; g_ah[1][i] = 0.f; g_ac[i] = 0.f;
        g_dh[0][i] = 0.f; g_dh[1][i] = 0.f; g_dc[i] = 0.f;
        if (i < BB*TXT) { g_aw[i] = 0.f; g_awc[i] = 0.f; }
        if (i < ENC*BB) g_ctx[i] = 0.f;
    }
    for (int i = blk*256 + tid; i < RNN*AD; i += NBLK*256)
        g_qWt[i] = queryW[(size_t)(i & 127)*RNN + (i >> 7)];
    for (int u = blk; u < MELT*BB; u += NBLK) {       // prenet L1 + L2 (same block)
        int t = u >> 5, b = u & 31;
        __syncthreads();
        if (tid < NMEL)
            x_s[tid] = (t == 0) ? 0.f : din[((size_t)(b*NMEL + tid))*MELT + t - 1];
        __syncthreads();
        float s = 0.f;
        const float* w = preW1 + (size_t)tid*NMEL;
        #pragma unroll
        for (int m = 0; m < NMEL; m++) s = fmaf(x_s[m], w[m], s);
        g_x1[(size_t)u*PRE + tid] = fmaxf(s, 0.f);
    }
    for (int u = blk; u < MELT*BB; u += NBLK) {
        int t = u >> 5, b = u & 31;
        __syncthreads();
        x_s[tid] = g_x1[(size_t)u*PRE + tid];          // written by this block above
        __syncthreads();
        float s = 0.f;
        const float* w = preW2 + (size_t)tid*PRE;
        #pragma unroll 8
        for (int k = 0; k < PRE; k++) s = fmaf(x_s[k], w[k], s);
        g_xpre[((size_t)t*PRE + tid)*BB + b] = fmaxf(s, 0.f);
    }
    for (int u = blk; u < BB*AD; u += NBLK) {         // processed memory: 2 tt per unit
        int b = u >> 7, t2 = (u & 127) << 1;
        __syncthreads();
        for (int i = tid; i < 2*ENC; i += 256)
            x_s[i] = memory[((size_t)(b*TXT + t2))*ENC + i];
        __syncthreads();
        int a = tid & 127, half = tid >> 7;
        float s = 0.f;
        const float* w = memW + (size_t)a*ENC;
        const float* xr = x_s + half*ENC;
        #pragma unroll 8
        for (int e = 0; e < ENC; e++) s = fmaf(xr[e], w[e], s);
        g_pm[(size_t)(b*TXT + t2 + half)*AD + a] = s;
    }
    gbar();

    // -------- 400-step sequential loop --------
    for (int t = 0; t < MELT; t++) {
        const int prev = t & 1, cur = prev ^ 1;

        // interval 1: D(t-1), A(t), location conv(t)
        if (t > 0)
            lstm_tile(dWi, 1536, dWh, dB,
                      g_ah[prev], RNN, g_ctx, ENC,
                      g_dh[cur], g_dc, g_dh[prev],
                      g_dhh + (size_t)(t-1)*RNN*BB, w_s, x_s, rowp);
        lstm_tile(aWi, 768, aWh, aB,
                  g_xpre + (size_t)t*PRE*BB, PRE, g_ctx, ENC,
                  g_ah[prev], g_ac, g_ah[cur], (float*)0, w_s, x_s, rowp);
        for (int q = 0; q < 2; q++) {                  // conv: 2 of 256 units per block
            int u = blk*2 + q, b2 = u >> 3, tth = (u & 7) << 5;
            float* a0 = x_s, *a1 = x_s + 64, *fs = x_s + 128;
            __syncthreads();
            if (tid < 62) {
                int idx = tth - 15 + tid;
                bool ok = (idx >= 0 && idx < TXT);
                a0[tid] = ok ? __ldcg(&g_aw [b2*TXT + idx]) : 0.f;
                a1[tid] = ok ? __ldcg(&g_awc[b2*TXT + idx]) : 0.f;
            }
            __syncthreads();
            {
                int ttl = tid & 31;
                #pragma unroll
                for (int qq = 0; qq < 4; qq++) {
                    int nf = (tid >> 5) + qq*8;
                    const float* c0 = cw_s + nf*62;
                    float s = 0.f;
                    #pragma unroll
                    for (int k = 0; k < 31; k++)
                        s += c0[k]*a0[ttl + k] + c0[31 + k]*a1[ttl + k];
                    fs[nf*33 + ttl] = s;
                }
            }
            __syncthreads();
            {
                int a = tid & 127, half = tid >> 7;
                float wr[32];
                #pragma unroll
                for (int nf = 0; nf < 32; nf++) wr[nf] = dW_s[a*32 + nf];
                #pragma unroll
                for (int tl = 0; tl < 16; tl++) {
                    int ttl = half*16 + tl;
                    float s = 0.f;
                    #pragma unroll
                    for (int nf = 0; nf < 32; nf++)
                        s = fmaf(wr[nf], fs[nf*33 + ttl], s);
                    g_loc[((size_t)(b2*TXT + tth + ttl))*AD + a] = s;
                }
            }
            __syncthreads();
        }
        gbar();

        // interval 2: attention (blocks 0..31, one per batch)
        if (blk < BB) {
            const int b = blk;
            float* ah_s = x_s;                     // 1024
            float* q_s = w_s, *v_s = w_s + 128, *red = w_s + 256, *aw_s = w_s + 512;
            const float* ahp = g_ah[cur];
            for (int k = tid; k < RNN; k += 256) ah_s[k] = __ldcg(ahp + k*32 + b);
            if (tid < AD) v_s[tid] = vW[tid];
            __syncthreads();
            {   // query projection: 2 halves x 128 a
                int a = tid & 127, half = tid >> 7;
                float s = 0.f;
                const float* qw = g_qWt + (size_t)half*512*AD + a;
                const float* ar = ah_s + half*512;
                #pragma unroll 8
                for (int k = 0; k < 512; k++) s = fmaf(qw[(size_t)k*AD], ar[k], s);
                red[tid] = s;
                __syncthreads();
                if (tid < 128) q_s[tid] = red[tid] + red[128 + tid];
            }
            __syncthreads();
            float e = 0.f;
            {
                const float4* lp = (const float4*)(g_loc + ((size_t)(b*TXT + tid))*AD);
                const float4* pp = (const float4*)(g_pm  + ((size_t)(b*TXT + tid))*AD);
                const float4* qp = (const float4*)q_s;
                const float4* vp = (const float4*)v_s;
                #pragma unroll 8
                for (int i = 0; i < 32; i++) {
                    float4 l = __ldcg(lp + i), p = pp[i], qv = qp[i], vv = vp[i];
                    e = fmaf(vv.x, tanha(l.x + qv.x + p.x), e);
                    e = fmaf(vv.y, tanha(l.y + qv.y + p.y), e);
                    e = fmaf(vv.z, tanha(l.z + qv.z + p.z), e);
                    e = fmaf(vv.w, tanha(l.w + qv.w + p.w), e);
                }
            }
            if (tid >= mlen[b]) e = NEGV;
            red[tid] = e; __syncthreads();
            for (int s2 = 128; s2 > 0; s2 >>= 1) {
                if (tid < s2) red[tid] = fmaxf(red[tid], red[tid + s2]);
                __syncthreads();
            }
            float mx = red[0]; __syncthreads();
            float ex = expf(e - mx);
            red[tid] = ex; __syncthreads();
            for (int s2 = 128; s2 > 0; s2 >>= 1) {
                if (tid < s2) red[tid] += red[tid + s2];
                __syncthreads();
            }
            float aw = ex / red[0];
            aw_s[tid] = aw;
            g_aw[b*TXT + tid] = aw;
            g_awc[b*TXT + tid] = __ldcg(&g_awc[b*TXT + tid]) + aw;
            out[ALIGN_OFF + ((size_t)b*MELT + t)*TXT + tid] = aw;
            __syncthreads();
            {   // context
                int e2 = tid << 1;
                const float* mb = memory + (size_t)b*TXT*ENC;
                float cx = 0.f, cy = 0.f;
                #pragma unroll 4
                for (int k = 0; k < TXT; k++) {
                    float w = aw_s[k];
                    float2 mv = *(const float2*)(mb + (size_t)k*ENC + e2);
                    cx = fmaf(w, mv.x, cx);
                    cy = fmaf(w, mv.y, cy);
                }
                g_ctx[(e2    )*32 + b] = cx;
                g_ctx[(e2 + 1)*32 + b] = cy;
                g_ctxh[((size_t)t*ENC + e2    )*32 + b] = cx;
                g_ctxh[((size_t)t*ENC + e2 + 1)*32 + b] = cy;
            }
            __syncthreads();
        }
        gbar();
    }

    // final decoder step D(399): virtual t=400 -> prev=0, cur=1
    lstm_tile(dWi, 1536, dWh, dB,
              g_ah[0], RNN, g_ctx, ENC,
              g_dh[1], g_dc, g_dh[0],
              g_dhh + (size_t)(MELT-1)*RNN*BB, w_s, x_s, rowp);
    gbar();

    // -------- epilogue: mel + gate projection for all steps --------
    for (int u = blk; u < MELT*3; u += NBLK) {
        int t = u / 3, rz = u - t*3;
        const int r = tid >> 3, b0 = (tid & 7) << 2, rg = rz*32 + r;
        __syncthreads();
        if (tid < 32) {
            int rr = rz*32 + tid;
            rowp[tid] = (rr < NMEL) ? projW + (size_t)rr*1536 : gateW;
        }
        __syncthreads();
        float bv = (rg < NMEL) ? projB[rg] : gateB[0];
        float4 acc = make_float4(bv, bv, bv, bv);
        gemm32db(acc, rowp, 0,    g_dhh  + (size_t)t*RNN*BB, RNN, w_s, x_s);
        gemm32db(acc, rowp, 1024, g_ctxh + (size_t)t*ENC*BB, ENC, w_s, x_s);
        if (rg < NMEL) {
            out[((size_t)(b0 + 0)*NMEL + rg)*MELT + t] = acc.x;
            out[((size_t)(b0 + 1)*NMEL + rg)*MELT + t] = acc.y;
            out[((size_t)(b0 + 2)*NMEL + rg)*MELT + t] = acc.z;
            out[((size_t)(b0 + 3)*NMEL + rg)*MELT + t] = acc.w;
        } else if (rg == NMEL) {
            out[GATE_OFF + (size_t)(b0 + 0)*MELT + t] = acc.x;
            out[GATE_OFF + (size_t)(b0 + 1)*MELT + t] = acc.y;
            out[GATE_OFF + (size_t)(b0 + 2)*MELT + t] = acc.z;
            out[GATE_OFF + (size_t)(b0 + 3)*MELT + t] = acc.w;
        }
        __syncthreads();
    }
}

extern "C" void kernel_launch(void* const* d_in, const int* in_sizes, int n_in,
                              void* d_out, int out_size)
{
    decoder_all<<<NBLK, 256>>>(
        (const float*)d_in[0],  (const float*)d_in[1],  (const int*)d_in[2],
        (const float*)d_in[3],  (const float*)d_in[4],
        (const float*)d_in[5],  (const float*)d_in[6],  (const float*)d_in[7],
        (const float*)d_in[8],  (const float*)d_in[9],  (const float*)d_in[10],
        (const float*)d_in[11], (const float*)d_in[12],
        (const float*)d_in[13], (const float*)d_in[14], (const float*)d_in[15],
        (const float*)d_in[16], (const float*)d_in[17],
        (const float*)d_in[18], (const float*)d_in[19],
        (float*)d_out);
}

// round 14
// speedup vs baseline: 1.0564x; 1.0564x over previous
#include <cuda_runtime.h>
#include <math.h>

#define BB   32
#define TXT  256
#define MELT 400
#define ENC  512
#define NMEL 80
#define PRE  256
#define RNN  1024
#define AD   128
#define NBLK 128
#define NTHR 512
#define NEGV (-1e9f)

#define GATE_OFF  (BB*NMEL*MELT)
#define ALIGN_OFF (GATE_OFF + BB*MELT)

// ---------------- device-global scratch (allocation-free) ----------------
__device__ float g_x1  [(size_t)MELT*BB*PRE];    // [u=t*32+b][p]
__device__ float g_xpre[(size_t)MELT*PRE*BB];    // [t][k][b]
__device__ float g_pm  [(size_t)BB*TXT*AD];      // [b][tt][a]
__device__ float g_loc [(size_t)BB*TXT*AD];      // [b][tt][a]
__device__ float g_qWt [(size_t)RNN*AD];         // [k][a]
__device__ float g_ah  [2][RNN*BB];              // [k][b]
__device__ float g_ac  [RNN*BB];
__device__ float g_dh  [2][RNN*BB];
__device__ float g_dc  [RNN*BB];
__device__ float g_aw  [BB*TXT];
__device__ float g_awc [BB*TXT];
__device__ float g_ctx [ENC*BB];                 // [k][b]
__device__ float g_dhh [(size_t)MELT*RNN*BB];    // [t][k][b]
__device__ float g_ctxh[(size_t)MELT*ENC*BB];    // [t][k][b]
// pre-transposed weights: [tile][k][32 rows-in-tile]
__device__ float g_aWiT[(size_t)128*768*32];
__device__ float g_aWhT[(size_t)128*1024*32];
__device__ float g_dWiT[(size_t)128*1536*32];
__device__ float g_dWhT[(size_t)128*1024*32];
__device__ float g_projT[(size_t)3*1536*32];
__device__ unsigned g_barc;
__device__ unsigned g_barg;

__device__ __forceinline__ float sigm(float x) { return 1.0f/(1.0f+expf(-x)); }
__device__ __forceinline__ float tanha(float x) {
    float y; asm("tanh.approx.f32 %0, %1;" : "=f"(y) : "f"(x)); return y;
}

__device__ __forceinline__ void gbar() {
    __syncthreads();
    if (threadIdx.x == 0) {
        __threadfence();
        unsigned gen = *(volatile unsigned*)&g_barg;
        if (atomicAdd(&g_barc, 1u) == NBLK - 1u) {
            g_barc = 0u;
            __threadfence();
            *(volatile unsigned*)&g_barg = gen + 1u;
        } else {
            while (*(volatile unsigned*)&g_barg == gen) { __nanosleep(64); }
        }
        __threadfence();
    }
    __syncthreads();
}

// 32 rows x 32 batch tile GEMM, 512 threads, transposed weights.
// wT: [K][32] contiguous (pre-transposed). X: [K][32] contiguous.
// thread: r = tid>>4 (row), b0 = (tid&15)*2 (2 batches). One sync per k-tile.
__device__ __forceinline__ void gemm32t(float2& acc,
    const float* __restrict__ wT, const float* __restrict__ X, int K,
    float* w_s /*2*1056*/, float* x_s /*2*1024*/)
{
    const int tid = threadIdx.x;
    const int r = tid >> 4, b0 = (tid & 15) << 1;
    const int i2 = tid << 1;
    const int wsi = (i2 >> 5)*33 + (i2 & 31);   // stride 33 is ODD: scalar stores only
    const int nt = K >> 5;
    float2 wv = *(const float2*)(wT + i2);
    float2 xv = __ldcg((const float2*)(X + i2));
    __syncthreads();                       // prior users of buffers done
    w_s[wsi] = wv.x; w_s[wsi + 1] = wv.y;  // scalar: avoids misaligned STS.64
    *(float2*)(x_s + i2) = xv;             // i2 even -> 8B aligned
    for (int kt = 0; kt < nt; kt++) {
        const int cur = kt & 1;
        if (kt + 1 < nt) {
            wv = *(const float2*)(wT + (size_t)(kt + 1)*1024 + i2);
            xv = __ldcg((const float2*)(X + (size_t)(kt + 1)*1024 + i2));
        }
        __syncthreads();                   // staged buffer cur visible
        const float* ws = w_s + cur*1056 + r;
        const float* xs = x_s + cur*1024 + b0;
        #pragma unroll
        for (int k2 = 0; k2 < 32; k2++) {
            float w = ws[k2*33];
            float2 x2 = *(const float2*)(xs + k2*32);
            acc.x = fmaf(w, x2.x, acc.x);
            acc.y = fmaf(w, x2.y, acc.y);
        }
        if (kt + 1 < nt) {                 // store into the other buffer: safe,
            const int nb = 1 - cur;        // all readers of it passed the sync
            float* wsn = w_s + nb*1056;
            wsn[wsi] = wv.x; wsn[wsi + 1] = wv.y;
            *(float2*)(x_s + nb*1024 + i2) = xv;
        }
    }
}

// one 32-gate-row tile of an LSTM step (this block's 8 h-units x 4 gates)
__device__ __forceinline__ void lstm_tile_t(
    const float* __restrict__ wiT, const float* __restrict__ X1, int K1,
    const float* __restrict__ X2, int K2,
    const float* __restrict__ whT, const float* __restrict__ hprev,
    const float* __restrict__ bias,
    float* __restrict__ cst, float* __restrict__ hout, float* __restrict__ hist,
    float* w_s, float* x_s)
{
    const int tid = threadIdx.x, blk = blockIdx.x;
    const int r = tid >> 4, b0 = (tid & 15) << 1;
    const int rg = (r >> 3)*RNN + blk*8 + (r & 7);
    float bv = bias[rg];
    float2 acc = make_float2(bv, bv);
    gemm32t(acc, wiT,                  X1,    K1,  w_s, x_s);
    gemm32t(acc, wiT + (size_t)K1*32,  X2,    K2,  w_s, x_s);
    gemm32t(acc, whT,                  hprev, RNN, w_s, x_s);
    __syncthreads();
    *(float2*)(x_s + r*32 + b0) = acc;     // even offsets -> aligned
    __syncthreads();
    if (tid < 256) {
        int j = tid >> 5, b = tid & 31, h = blk*8 + j;
        float iv = x_s[( 0 + j)*32 + b];
        float fv = x_s[( 8 + j)*32 + b];
        float gv = x_s[(16 + j)*32 + b];
        float ov = x_s[(24 + j)*32 + b];
        float c  = sigm(fv)*cst[h*32 + b] + sigm(iv)*tanhf(gv);
        float hn = sigm(ov)*tanhf(c);
        cst[h*32 + b] = c;
        hout[h*32 + b] = hn;
        if (hist) hist[h*32 + b] = hn;
    }
    __syncthreads();
}

__global__ __launch_bounds__(NTHR, 1) void decoder_all(
    const float* __restrict__ memory, const float* __restrict__ din,
    const int* __restrict__ mlen,
    const float* __restrict__ preW1, const float* __restrict__ preW2,
    const float* __restrict__ aWi, const float* __restrict__ aWh,
    const float* __restrict__ aB,
    const float* __restrict__ convW, const float* __restrict__ denseW,
    const float* __restrict__ queryW, const float* __restrict__ memW,
    const float* __restrict__ vW,
    const float* __restrict__ dWi, const float* __restrict__ dWh,
    const float* __restrict__ dB,
    const float* __restrict__ projW, const float* __restrict__ projB,
    const float* __restrict__ gateW, const float* __restrict__ gateB,
    float* __restrict__ out)
{
    __shared__ __align__(16) float w_s[2112];
    __shared__ __align__(16) float x_s[2048];
    __shared__ __align__(16) float cw_s[1984];
    __shared__ __align__(16) float dW_s[4096];
    const int blk = blockIdx.x, tid = threadIdx.x;
    const int gt = blk*NTHR + tid;          // 0..65535

    for (int i = tid; i < 1984; i += NTHR) cw_s[i] = convW[i];
    for (int i = tid; i < 4096; i += NTHR) dW_s[i] = denseW[i];

    // ================= prologue (single interval) =================
    for (int i = gt; i < RNN*BB; i += NBLK*NTHR) {
        g_ah[0][i] = 0.f; g_ah[1][i] = 0.f; g_ac[i] = 0.f;
        g_dh[0][i] = 0.f; g_dh[1][i] = 0.f; g_dc[i] = 0.f;
        if (i < BB*TXT) { g_aw[i] = 0.f; g_awc[i] = 0.f; }
        if (i < ENC*BB) g_ctx[i] = 0.f;
    }
    for (int i = gt; i < RNN*AD; i += NBLK*NTHR)
        g_qWt[i] = queryW[(size_t)(i & 127)*RNN + (i >> 7)];
    // weight transposes: read-coalesced, scatter writes (L2-absorbed)
    {
        const size_t nA = (size_t)128*32*768;
        for (size_t i = gt; i < nA; i += NBLK*NTHR) {
            int k = (int)(i % 768); size_t rem = i / 768;
            int j = (int)(rem & 31); int tile = (int)(rem >> 5);
            int rg = (j >> 3)*RNN + tile*8 + (j & 7);
            g_aWiT[((size_t)tile*768 + k)*32 + j] = aWi[(size_t)rg*768 + k];
        }
        const size_t nH = (size_t)128*32*1024;
        for (size_t i = gt; i < nH; i += NBLK*NTHR) {
            int k = (int)(i & 1023); size_t rem = i >> 10;
            int j = (int)(rem & 31); int tile = (int)(rem >> 5);
            int rg = (j >> 3)*RNN + tile*8 + (j & 7);
            g_aWhT[((size_t)tile*1024 + k)*32 + j] = aWh[(size_t)rg*1024 + k];
            g_dWhT[((size_t)tile*1024 + k)*32 + j] = dWh[(size_t)rg*1024 + k];
        }
        const size_t nD = (size_t)128*32*1536;
        for (size_t i = gt; i < nD; i += NBLK*NTHR) {
            int k = (int)(i % 1536); size_t rem = i / 1536;
            int j = (int)(rem & 31); int tile = (int)(rem >> 5);
            int rg = (j >> 3)*RNN + tile*8 + (j & 7);
            g_dWiT[((size_t)tile*1536 + k)*32 + j] = dWi[(size_t)rg*1536 + k];
        }
        const size_t nP = (size_t)3*32*1536;
        for (size_t i = gt; i < nP; i += NBLK*NTHR) {
            int k = (int)(i % 1536); size_t rem = i / 1536;
            int j = (int)(rem & 31); int rz = (int)(rem >> 5);
            int rr = rz*32 + j;
            float v = 0.f;
            if (rr < NMEL)      v = projW[(size_t)rr*1536 + k];
            else if (rr == NMEL) v = gateW[k];
            g_projT[((size_t)rz*1536 + k)*32 + j] = v;
        }
    }
    // prenet layer 1 (2 units per block-iteration)
    for (int u0 = blk*2; u0 < MELT*BB; u0 += NBLK*2) {
        int half = tid >> 8, tid2 = tid & 255;
        int u = u0 + half, t = u >> 5, b = u & 31;
        float* fr = x_s + half*1024;
        __syncthreads();
        if (tid2 < NMEL)
            fr[tid2] = (t == 0) ? 0.f : din[((size_t)(b*NMEL + tid2))*MELT + t - 1];
        __syncthreads();
        float s = 0.f;
        const float* w = preW1 + (size_t)tid2*NMEL;
        #pragma unroll
        for (int m = 0; m < NMEL; m++) s = fmaf(fr[m], w[m], s);
        g_x1[(size_t)u*PRE + tid2] = fmaxf(s, 0.f);
    }
    // prenet layer 2 (writes [t][k][b])
    for (int u0 = blk*2; u0 < MELT*BB; u0 += NBLK*2) {
        int half = tid >> 8, tid2 = tid & 255;
        int u = u0 + half, t = u >> 5, b = u & 31;
        float* xr = x_s + half*1024;
        __syncthreads();
        xr[tid2] = g_x1[(size_t)u*PRE + tid2];   // written by this block above
        __syncthreads();
        float s = 0.f;
        const float* w = preW2 + (size_t)tid2*PRE;
        #pragma unroll 8
        for (int k = 0; k < PRE; k++) s = fmaf(xr[k], w[k], s);
        g_xpre[((size_t)t*PRE + tid2)*BB + b] = fmaxf(s, 0.f);
    }
    // processed memory: unit = (b, 4 tt rows)
    for (int u = blk; u < BB*64; u += NBLK) {
        int b = u >> 6, tt4 = (u & 63) << 2;
        __syncthreads();
        for (int i = tid; i < 4*ENC; i += NTHR)
            x_s[i] = memory[((size_t)(b*TXT + tt4))*ENC + i];
        __syncthreads();
        int a = tid & 127, tl = tid >> 7;
        float s = 0.f;
        const float* w = memW + (size_t)a*ENC;
        const float* xr = x_s + tl*ENC;
        #pragma unroll 8
        for (int e = 0; e < ENC; e++) s = fmaf(xr[e], w[e], s);
        g_pm[((size_t)(b*TXT + tt4 + tl))*AD + a] = s;
    }
    gbar();

    // ================= 400-step sequential loop =================
    for (int t = 0; t < MELT; t++) {
        const int prev = t & 1, cur = prev ^ 1;

        // ---- interval 1: D(t-1), A(t), location conv(t) ----
        if (t > 0)
            lstm_tile_t(g_dWiT + (size_t)blk*1536*32,
                        g_ah[prev], RNN, g_ctx, ENC,
                        g_dWhT + (size_t)blk*1024*32, g_dh[cur],
                        dB, g_dc, g_dh[prev],
                        g_dhh + (size_t)(t-1)*RNN*BB, w_s, x_s);
        lstm_tile_t(g_aWiT + (size_t)blk*768*32,
                    g_xpre + (size_t)t*PRE*BB, PRE, g_ctx, ENC,
                    g_aWhT + (size_t)blk*1024*32, g_ah[prev],
                    aB, g_ac, g_ah[cur], (float*)0, w_s, x_s);
        {   // conv: 2 units (of 256) per block, both halves in parallel
            int q = tid >> 8, tid2 = tid & 255;
            int u = blk*2 + q, b2 = u >> 3, tth = (u & 7) << 5;
            float* base = q ? w_s : x_s;        // each >= 1184 floats
            float* a0 = base, *a1 = base + 64, *fs = base + 128;
            __syncthreads();
            if (tid2 < 62) {
                int idx = tth - 15 + tid2;
                bool ok = (idx >= 0 && idx < TXT);
                a0[tid2] = ok ? __ldcg(&g_aw [b2*TXT + idx]) : 0.f;
                a1[tid2] = ok ? __ldcg(&g_awc[b2*TXT + idx]) : 0.f;
            }
            __syncthreads();
            {
                int ttl = tid2 & 31;
                #pragma unroll
                for (int qq = 0; qq < 4; qq++) {
                    int nf = (tid2 >> 5) + qq*8;
                    const float* c0 = cw_s + nf*62;
                    float s = 0.f;
                    #pragma unroll
                    for (int k = 0; k < 31; k++)
                        s += c0[k]*a0[ttl + k] + c0[31 + k]*a1[ttl + k];
                    fs[nf*33 + ttl] = s;
                }
            }
            __syncthreads();
            {
                int a = tid2 & 127, hf = tid2 >> 7;
                float wr[32];
                #pragma unroll
                for (int nf = 0; nf < 32; nf++) wr[nf] = dW_s[a*32 + nf];
                #pragma unroll
                for (int tl = 0; tl < 16; tl++) {
                    int ttl = hf*16 + tl;
                    float s = 0.f;
                    #pragma unroll
                    for (int nf = 0; nf < 32; nf++)
                        s = fmaf(wr[nf], fs[nf*33 + ttl], s);
                    g_loc[((size_t)(b2*TXT + tth + ttl))*AD + a] = s;
                }
            }
            __syncthreads();
        }
        gbar();

        // ---- interval 2: attention (blocks 0..31, one per batch) ----
        if (blk < BB) {
            const int b = blk;
            float* ah_s = x_s;                  // 1024
            float* q_s = w_s, *v_s = w_s + 128, *red = w_s + 256, *aw_s = w_s + 768;
            const float* ahp = g_ah[cur];
            for (int k = tid; k < RNN; k += NTHR) ah_s[k] = __ldcg(ahp + k*32 + b);
            if (tid < AD) v_s[tid] = vW[tid];
            __syncthreads();
            {   // query projection: 4 quarters x 128 a
                int a = tid & 127, qr = tid >> 7;
                float s = 0.f;
                const float* qw = g_qWt + (size_t)qr*256*AD + a;
                const float* ar = ah_s + qr*256;
                #pragma unroll 8
                for (int k = 0; k < 256; k++) s = fmaf(qw[(size_t)k*AD], ar[k], s);
                red[tid] = s;
                __syncthreads();
                if (tid < 128)
                    q_s[tid] = red[tid] + red[128 + tid] + red[256 + tid] + red[384 + tid];
            }
            __syncthreads();
            float e = NEGV;
            if (tid < TXT) {
                const float4* lp = (const float4*)(g_loc + ((size_t)(b*TXT + tid))*AD);
                const float4* pp = (const float4*)(g_pm  + ((size_t)(b*TXT + tid))*AD);
                const float4* qp = (const float4*)q_s;
                const float4* vp = (const float4*)v_s;
                float ee = 0.f;
                #pragma unroll 8
                for (int i = 0; i < 32; i++) {
                    float4 l = __ldcg(lp + i), p = pp[i], qv = qp[i], vv = vp[i];
                    ee = fmaf(vv.x, tanha(l.x + qv.x + p.x), ee);
                    ee = fmaf(vv.y, tanha(l.y + qv.y + p.y), ee);
                    ee = fmaf(vv.z, tanha(l.z + qv.z + p.z), ee);
                    ee = fmaf(vv.w, tanha(l.w + qv.w + p.w), ee);
                }
                e = (tid >= mlen[b]) ? NEGV : ee;
            }
            red[tid] = e; __syncthreads();
            for (int s2 = 256; s2 > 0; s2 >>= 1) {
                if (tid < s2) red[tid] = fmaxf(red[tid], red[tid + s2]);
                __syncthreads();
            }
            float mx = red[0]; __syncthreads();
            float ex = (tid < TXT) ? expf(e - mx) : 0.f;
            red[tid] = ex; __syncthreads();
            for (int s2 = 256; s2 > 0; s2 >>= 1) {
                if (tid < s2) red[tid] += red[tid + s2];
                __syncthreads();
            }
            float inv = 1.0f / red[0];
            if (tid < TXT) {
                float aw = ex * inv;
                aw_s[tid] = aw;
                g_aw[b*TXT + tid] = aw;
                g_awc[b*TXT + tid] = __ldcg(&g_awc[b*TXT + tid]) + aw;
                out[ALIGN_OFF + ((size_t)b*MELT + t)*TXT + tid] = aw;
            }
            __syncthreads();
            {   // context: one ENC element per thread
                int e2 = tid;
                const float* mb = memory + (size_t)b*TXT*ENC + e2;
                float cx = 0.f;
                #pragma unroll 8
                for (int k = 0; k < TXT; k++)
                    cx = fmaf(aw_s[k], mb[(size_t)k*ENC], cx);
                g_ctx[e2*32 + b] = cx;
                g_ctxh[((size_t)t*ENC + e2)*32 + b] = cx;
            }
            __syncthreads();
        }
        gbar();
    }

    // final decoder step D(399): virtual t=400 -> prev=0, cur=1
    lstm_tile_t(g_dWiT + (size_t)blk*1536*32,
                g_ah[0], RNN, g_ctx, ENC,
                g_dWhT + (size_t)blk*1024*32, g_dh[1],
                dB, g_dc, g_dh[0],
                g_dhh + (size_t)(MELT-1)*RNN*BB, w_s, x_s);
    gbar();

    // ================= epilogue: mel + gate projection =================
    for (int u = blk; u < MELT*3; u += NBLK) {
        int t = u / 3, rz = u - t*3;
        const int r = tid >> 4, b0 = (tid & 15) << 1, rg = rz*32 + r;
        float bv = (rg < NMEL) ? projB[rg] : ((rg == NMEL) ? gateB[0] : 0.f);
        float2 acc = make_float2(bv, bv);
        gemm32t(acc, g_projT + (size_t)rz*1536*32,
                g_dhh + (size_t)t*RNN*BB, RNN, w_s, x_s);
        gemm32t(acc, g_projT + ((size_t)rz*1536 + RNN)*32,
                g_ctxh + (size_t)t*ENC*BB, ENC, w_s, x_s);
        if (rg < NMEL) {
            out[((size_t)(b0 + 0)*NMEL + rg)*MELT + t] = acc.x;
            out[((size_t)(b0 + 1)*NMEL + rg)*MELT + t] = acc.y;
        } else if (rg == NMEL) {
            out[GATE_OFF + (size_t)(b0 + 0)*MELT + t] = acc.x;
            out[GATE_OFF + (size_t)(b0 + 1)*MELT + t] = acc.y;
        }
        __syncthreads();
    }
}

extern "C" void kernel_launch(void* const* d_in, const int* in_sizes, int n_in,
                              void* d_out, int out_size)
{
    decoder_all<<<NBLK, NTHR>>>(
        (const float*)d_in[0],  (const float*)d_in[1],  (const int*)d_in[2],
        (const float*)d_in[3],  (const float*)d_in[4],
        (const float*)d_in[5],  (const float*)d_in[6],  (const float*)d_in[7],
        (const float*)d_in[8],  (const float*)d_in[9],  (const float*)d_in[10],
        (const float*)d_in[11], (const float*)d_in[12],
        (const float*)d_in[13], (const float*)d_in[14], (const float*)d_in[15],
        (const float*)d_in[16], (const float*)d_in[17],
        (const float*)d_in[18], (const float*)d_in[19],
        (float*)d_out);
}

// round 15
// speedup vs baseline: 1.1156x; 1.0560x over previous
#include <cuda_runtime.h>
#include <math.h>

#define BB   32
#define TXT  256
#define MELT 400
#define ENC  512
#define NMEL 80
#define PRE  256
#define RNN  1024
#define AD   128
#define NBLK 128
#define NTHR 512
#define NEGV (-1e9f)

#define GATE_OFF  (BB*NMEL*MELT)
#define ALIGN_OFF (GATE_OFF + BB*MELT)

// ---------------- device-global scratch (allocation-free) ----------------
__device__ float g_x1  [(size_t)MELT*BB*PRE];    // [u=t*32+b][p]
__device__ float g_xpre[(size_t)MELT*PRE*BB];    // [t][k][b]
__device__ float g_pm  [(size_t)BB*TXT*AD];      // [b][tt][a]
__device__ float g_loc [(size_t)BB*TXT*AD];      // [b][tt][a]
__device__ float g_qWt [(size_t)RNN*AD];         // [k][a]
__device__ float g_ah  [2][RNN*BB];              // [k][b]
__device__ float g_ac  [RNN*BB];
__device__ float g_dh  [2][RNN*BB];
__device__ float g_dc  [RNN*BB];
__device__ float g_aw  [BB*TXT];
__device__ float g_awc [BB*TXT];
__device__ float g_ctx [ENC*BB];                 // [k][b]
__device__ float g_dhh [(size_t)MELT*RNN*BB];    // [t][k][b]
__device__ float g_ctxh[(size_t)MELT*ENC*BB];    // [t][k][b]
// pre-transposed weights: [tile][k][64 rows-in-tile]
__device__ float g_aWiT[(size_t)64*768*64];
__device__ float g_aWhT[(size_t)64*1024*64];
__device__ float g_dWiT[(size_t)64*1536*64];
__device__ float g_dWhT[(size_t)64*1024*64];
__device__ float g_projT[(size_t)2*1536*64];
__device__ unsigned g_barc;
__device__ unsigned g_barg;

__device__ __forceinline__ float sigm(float x) { return 1.0f/(1.0f+expf(-x)); }
__device__ __forceinline__ float tanha(float x) {
    float y; asm("tanh.approx.f32 %0, %1;" : "=f"(y) : "f"(x)); return y;
}

__device__ __forceinline__ void gbar() {
    __syncthreads();
    if (threadIdx.x == 0) {
        __threadfence();
        unsigned gen = *(volatile unsigned*)&g_barg;
        if (atomicAdd(&g_barc, 1u) == NBLK - 1u) {
            g_barc = 0u;
            __threadfence();
            *(volatile unsigned*)&g_barg = gen + 1u;
        } else {
            while (*(volatile unsigned*)&g_barg == gen) { __nanosleep(64); }
        }
        __threadfence();
    }
    __syncthreads();
}

// 64 rows x 32 batch tile GEMM, 512 threads, transposed weights.
// wT: [K][64] contiguous. X: [K][32] contiguous. One sync per k-tile.
// thread: r = tid>>3 (row 0..63), b0 = (tid&7)*4 (4 batches).
__device__ __forceinline__ void gemm64(float4& acc,
    const float* __restrict__ wT, const float* __restrict__ X, int K,
    float* w_s /*2*2048*/, float* x_s /*2*1024*/)
{
    const int tid = threadIdx.x;
    const int r = tid >> 3, b0 = (tid & 7) << 2;
    const int i4 = tid << 2;               // w staging: 2048 floats / 512 thr
    const int i2 = tid << 1;               // x staging: 1024 floats / 512 thr
    const int nt = K >> 5;
    float4 wv = *(const float4*)(wT + i4);
    float2 xv = __ldcg((const float2*)(X + i2));
    __syncthreads();                       // prior users of buffers done
    *(float4*)(w_s + i4) = wv;             // aligned, conflict-free
    *(float2*)(x_s + i2) = xv;
    for (int kt = 0; kt < nt; kt++) {
        const int cur = kt & 1;
        if (kt + 1 < nt) {
            wv = *(const float4*)(wT + (size_t)(kt + 1)*2048 + i4);
            xv = __ldcg((const float2*)(X + (size_t)(kt + 1)*1024 + i2));
        }
        __syncthreads();                   // staged buffer cur visible
        const float* ws = w_s + cur*2048 + r;
        const float* xs = x_s + cur*1024 + b0;
        #pragma unroll
        for (int k2 = 0; k2 < 32; k2++) {
            float w = ws[k2*64];           // <=4 distinct addrs/warp: broadcast
            float4 x4 = *(const float4*)(xs + k2*32);  // 128B/warp, bcast x4
            acc.x = fmaf(w, x4.x, acc.x);
            acc.y = fmaf(w, x4.y, acc.y);
            acc.z = fmaf(w, x4.z, acc.z);
            acc.w = fmaf(w, x4.w, acc.w);
        }
        if (kt + 1 < nt) {                 // other buffer: readers passed sync
            const int nb = 1 - cur;
            *(float4*)(w_s + nb*2048 + i4) = wv;
            *(float2*)(x_s + nb*1024 + i2) = xv;
        }
    }
}

// one 64-gate-row tile (16 h-units x 4 gates) of an LSTM step
__device__ __forceinline__ void lstm64(
    const float* __restrict__ wiT, const float* __restrict__ X1, int K1,
    const float* __restrict__ X2, int K2,
    const float* __restrict__ whT, const float* __restrict__ hprev,
    const float* __restrict__ bias, int u0,
    float* __restrict__ cst, float* __restrict__ hout, float* __restrict__ hist,
    float* w_s, float* x_s)
{
    const int tid = threadIdx.x;
    const int r = tid >> 3, b0 = (tid & 7) << 2;
    const int rg = (r >> 4)*RNN + u0 + (r & 15);
    float bv = bias[rg];
    float4 acc = make_float4(bv, bv, bv, bv);
    gemm64(acc, wiT,                 X1,    K1,  w_s, x_s);
    gemm64(acc, wiT + (size_t)K1*64, X2,    K2,  w_s, x_s);
    gemm64(acc, whT,                 hprev, RNN, w_s, x_s);
    __syncthreads();
    *(float4*)(x_s + r*32 + b0) = acc;     // 64x32 = full 2048-float x_s
    __syncthreads();
    {
        int j = tid >> 5, b = tid & 31, h = u0 + j;   // 16 units x 32 batch
        float iv = x_s[(     j)*32 + b];
        float fv = x_s[(16 + j)*32 + b];
        float gv = x_s[(32 + j)*32 + b];
        float ov = x_s[(48 + j)*32 + b];
        float c  = sigm(fv)*cst[h*32 + b] + sigm(iv)*tanhf(gv);
        float hn = sigm(ov)*tanhf(c);
        cst[h*32 + b] = c;
        hout[h*32 + b] = hn;
        if (hist) hist[h*32 + b] = hn;
    }
    __syncthreads();
}

__global__ __launch_bounds__(NTHR, 1) void decoder_all(
    const float* __restrict__ memory, const float* __restrict__ din,
    const int* __restrict__ mlen,
    const float* __restrict__ preW1, const float* __restrict__ preW2,
    const float* __restrict__ aWi, const float* __restrict__ aWh,
    const float* __restrict__ aB,
    const float* __restrict__ convW, const float* __restrict__ denseW,
    const float* __restrict__ queryW, const float* __restrict__ memW,
    const float* __restrict__ vW,
    const float* __restrict__ dWi, const float* __restrict__ dWh,
    const float* __restrict__ dB,
    const float* __restrict__ projW, const float* __restrict__ projB,
    const float* __restrict__ gateW, const float* __restrict__ gateB,
    float* __restrict__ out)
{
    __shared__ __align__(16) float w_s[4096];
    __shared__ __align__(16) float x_s[2048];
    __shared__ __align__(16) float cw_s[1984];
    __shared__ __align__(16) float dW_s[4096];   // [nf][128] transposed
    const int blk = blockIdx.x, tid = threadIdx.x;
    const int gt = blk*NTHR + tid;

    for (int i = tid; i < 1984; i += NTHR) cw_s[i] = convW[i];
    for (int i = tid; i < 4096; i += NTHR) {
        int nf = i >> 7, a = i & 127;
        dW_s[i] = denseW[a*32 + nf];             // conflict-free reads later
    }

    // ================= prologue (single interval) =================
    for (int i = gt; i < RNN*BB; i += NBLK*NTHR) {
        g_ah[0][i] = 0.f; g_ah[1][i] = 0.f; g_ac[i] = 0.f;
        g_dh[0][i] = 0.f; g_dh[1][i] = 0.f; g_dc[i] = 0.f;
        if (i < BB*TXT) { g_aw[i] = 0.f; g_awc[i] = 0.f; }
        if (i < ENC*BB) g_ctx[i] = 0.f;
    }
    for (int i = gt; i < RNN*AD; i += NBLK*NTHR)
        g_qWt[i] = queryW[(size_t)(i & 127)*RNN + (i >> 7)];
    // weight transposes into [tile][k][64] (coalesced reads, L2-merged writes)
    {
        const size_t nA = (size_t)64*64*768;
        for (size_t i = gt; i < nA; i += NBLK*NTHR) {
            int k = (int)(i % 768); size_t rem = i / 768;
            int j = (int)(rem & 63); int tile = (int)(rem >> 6);
            int rg = (j >> 4)*RNN + tile*16 + (j & 15);
            g_aWiT[((size_t)tile*768 + k)*64 + j] = aWi[(size_t)rg*768 + k];
        }
        const size_t nH = (size_t)64*64*1024;
        for (size_t i = gt; i < nH; i += NBLK*NTHR) {
            int k = (int)(i & 1023); size_t rem = i >> 10;
            int j = (int)(rem & 63); int tile = (int)(rem >> 6);
            int rg = (j >> 4)*RNN + tile*16 + (j & 15);
            g_aWhT[((size_t)tile*1024 + k)*64 + j] = aWh[(size_t)rg*1024 + k];
            g_dWhT[((size_t)tile*1024 + k)*64 + j] = dWh[(size_t)rg*1024 + k];
        }
        const size_t nD = (size_t)64*64*1536;
        for (size_t i = gt; i < nD; i += NBLK*NTHR) {
            int k = (int)(i % 1536); size_t rem = i / 1536;
            int j = (int)(rem & 63); int tile = (int)(rem >> 6);
            int rg = (j >> 4)*RNN + tile*16 + (j & 15);
            g_dWiT[((size_t)tile*1536 + k)*64 + j] = dWi[(size_t)rg*1536 + k];
        }
        const size_t nP = (size_t)2*64*1536;
        for (size_t i = gt; i < nP; i += NBLK*NTHR) {
            int k = (int)(i % 1536); size_t rem = i / 1536;
            int j = (int)(rem & 63); int rz = (int)(rem >> 6);
            int rr = rz*64 + j;
            float v = 0.f;
            if (rr < NMEL)       v = projW[(size_t)rr*1536 + k];
            else if (rr == NMEL) v = gateW[k];
            g_projT[((size_t)rz*1536 + k)*64 + j] = v;
        }
    }
    // prenet layer 1 (2 units per block-iteration)
    for (int u0 = blk*2; u0 < MELT*BB; u0 += NBLK*2) {
        int half = tid >> 8, tid2 = tid & 255;
        int u = u0 + half, t = u >> 5, b = u & 31;
        float* fr = x_s + half*1024;
        __syncthreads();
        if (tid2 < NMEL)
            fr[tid2] = (t == 0) ? 0.f : din[((size_t)(b*NMEL + tid2))*MELT + t - 1];
        __syncthreads();
        float s = 0.f;
        const float* w = preW1 + (size_t)tid2*NMEL;
        #pragma unroll
        for (int m = 0; m < NMEL; m++) s = fmaf(fr[m], w[m], s);
        g_x1[(size_t)u*PRE + tid2] = fmaxf(s, 0.f);
    }
    // prenet layer 2 (writes [t][k][b])
    for (int u0 = blk*2; u0 < MELT*BB; u0 += NBLK*2) {
        int half = tid >> 8, tid2 = tid & 255;
        int u = u0 + half, t = u >> 5, b = u & 31;
        float* xr = x_s + half*1024;
        __syncthreads();
        xr[tid2] = g_x1[(size_t)u*PRE + tid2];   // written by this block above
        __syncthreads();
        float s = 0.f;
        const float* w = preW2 + (size_t)tid2*PRE;
        #pragma unroll 8
        for (int k = 0; k < PRE; k++) s = fmaf(xr[k], w[k], s);
        g_xpre[((size_t)t*PRE + tid2)*BB + b] = fmaxf(s, 0.f);
    }
    // processed memory: unit = (b, 4 tt rows)
    for (int u = blk; u < BB*64; u += NBLK) {
        int b = u >> 6, tt4 = (u & 63) << 2;
        __syncthreads();
        for (int i = tid; i < 4*ENC; i += NTHR)
            x_s[i] = memory[((size_t)(b*TXT + tt4))*ENC + i];
        __syncthreads();
        int a = tid & 127, tl = tid >> 7;
        float s = 0.f;
        const float* w = memW + (size_t)a*ENC;
        const float* xr = x_s + tl*ENC;
        #pragma unroll 8
        for (int e = 0; e < ENC; e++) s = fmaf(xr[e], w[e], s);
        g_pm[((size_t)(b*TXT + tt4 + tl))*AD + a] = s;
    }
    gbar();

    // ================= 400-step sequential loop =================
    for (int t = 0; t < MELT; t++) {
        const int prev = t & 1, cur = prev ^ 1;

        // ---- interval 1: A(t) on blocks 0-63 || D(t-1) on blocks 64-127 ----
        if (blk < 64) {
            lstm64(g_aWiT + (size_t)blk*768*64,
                   g_xpre + (size_t)t*PRE*BB, PRE, g_ctx, ENC,
                   g_aWhT + (size_t)blk*1024*64, g_ah[prev],
                   aB, blk*16, g_ac, g_ah[cur], (float*)0, w_s, x_s);
        } else if (t > 0) {
            int bd = blk - 64;
            lstm64(g_dWiT + (size_t)bd*1536*64,
                   g_ah[prev], RNN, g_ctx, ENC,
                   g_dWhT + (size_t)bd*1024*64, g_dh[cur],
                   dB, bd*16, g_dc, g_dh[prev],
                   g_dhh + (size_t)(t-1)*RNN*BB, w_s, x_s);
        }
        {   // conv: 2 units (of 256) per block, both halves in parallel
            int q = tid >> 8, tid2 = tid & 255;
            int u = blk*2 + q, b2 = u >> 3, tth = (u & 7) << 5;
            float* base = q ? w_s : x_s;        // each >= 1184 floats
            float* a0 = base, *a1 = base + 64, *fs = base + 128;
            __syncthreads();
            if (tid2 < 62) {
                int idx = tth - 15 + tid2;
                bool ok = (idx >= 0 && idx < TXT);
                a0[tid2] = ok ? __ldcg(&g_aw [b2*TXT + idx]) : 0.f;
                a1[tid2] = ok ? __ldcg(&g_awc[b2*TXT + idx]) : 0.f;
            }
            __syncthreads();
            {
                int ttl = tid2 & 31;
                #pragma unroll
                for (int qq = 0; qq < 4; qq++) {
                    int nf = (tid2 >> 5) + qq*8;
                    const float* c0 = cw_s + nf*62;
                    float s = 0.f;
                    #pragma unroll
                    for (int k = 0; k < 31; k++)
                        s += c0[k]*a0[ttl + k] + c0[31 + k]*a1[ttl + k];
                    fs[nf*33 + ttl] = s;
                }
            }
            __syncthreads();
            {
                int a = tid2 & 127, hf = tid2 >> 7;
                float wr[32];
                #pragma unroll
                for (int nf = 0; nf < 32; nf++) wr[nf] = dW_s[nf*128 + a];
                #pragma unroll
                for (int tl = 0; tl < 16; tl++) {
                    int ttl = hf*16 + tl;
                    float s = 0.f;
                    #pragma unroll
                    for (int nf = 0; nf < 32; nf++)
                        s = fmaf(wr[nf], fs[nf*33 + ttl], s);
                    g_loc[((size_t)(b2*TXT + tth + ttl))*AD + a] = s;
                }
            }
            __syncthreads();
        }
        gbar();

        // ---- interval 2: attention (blocks 0..31, one per batch) ----
        if (blk < BB) {
            const int b = blk;
            float* ah_s = x_s;                  // 1024
            float* q_s = w_s, *v_s = w_s + 128, *red = w_s + 256, *aw_s = w_s + 768;
            const float* ahp = g_ah[cur];
            for (int k = tid; k < RNN; k += NTHR) ah_s[k] = __ldcg(ahp + k*32 + b);
            if (tid < AD) v_s[tid] = vW[tid];
            __syncthreads();
            {   // query projection: 4 quarters x 128 a
                int a = tid & 127, qr = tid >> 7;
                float s = 0.f;
                const float* qw = g_qWt + (size_t)qr*256*AD + a;
                const float* ar = ah_s + qr*256;
                #pragma unroll 8
                for (int k = 0; k < 256; k++) s = fmaf(qw[(size_t)k*AD], ar[k], s);
                red[tid] = s;
                __syncthreads();
                if (tid < 128)
                    q_s[tid] = red[tid] + red[128 + tid] + red[256 + tid] + red[384 + tid];
            }
            __syncthreads();
            float e = NEGV;
            if (tid < TXT) {
                const float4* lp = (const float4*)(g_loc + ((size_t)(b*TXT + tid))*AD);
                const float4* pp = (const float4*)(g_pm  + ((size_t)(b*TXT + tid))*AD);
                const float4* qp = (const float4*)q_s;
                const float4* vp = (const float4*)v_s;
                float ee = 0.f;
                #pragma unroll 8
                for (int i = 0; i < 32; i++) {
                    float4 l = __ldcg(lp + i), p = pp[i], qv = qp[i], vv = vp[i];
                    ee = fmaf(vv.x, tanha(l.x + qv.x + p.x), ee);
                    ee = fmaf(vv.y, tanha(l.y + qv.y + p.y), ee);
                    ee = fmaf(vv.z, tanha(l.z + qv.z + p.z), ee);
                    ee = fmaf(vv.w, tanha(l.w + qv.w + p.w), ee);
                }
                e = (tid >= mlen[b]) ? NEGV : ee;
            }
            red[tid] = e; __syncthreads();
            for (int s2 = 256; s2 > 0; s2 >>= 1) {
                if (tid < s2) red[tid] = fmaxf(red[tid], red[tid + s2]);
                __syncthreads();
            }
            float mx = red[0]; __syncthreads();
            float ex = (tid < TXT) ? expf(e - mx) : 0.f;
            red[tid] = ex; __syncthreads();
            for (int s2 = 256; s2 > 0; s2 >>= 1) {
                if (tid < s2) red[tid] += red[tid + s2];
                __syncthreads();
            }
            float inv = 1.0f / red[0];
            if (tid < TXT) {
                float aw = ex * inv;
                aw_s[tid] = aw;
                g_aw[b*TXT + tid] = aw;
                g_awc[b*TXT + tid] = __ldcg(&g_awc[b*TXT + tid]) + aw;
                out[ALIGN_OFF + ((size_t)b*MELT + t)*TXT + tid] = aw;
            }
            __syncthreads();
            {   // context: one ENC element per thread
                int e2 = tid;
                const float* mb = memory + (size_t)b*TXT*ENC + e2;
                float cx = 0.f;
                #pragma unroll 8
                for (int k = 0; k < TXT; k++)
                    cx = fmaf(aw_s[k], mb[(size_t)k*ENC], cx);
                g_ctx[e2*32 + b] = cx;
                g_ctxh[((size_t)t*ENC + e2)*32 + b] = cx;
            }
            __syncthreads();
        }
        gbar();
    }

    // final decoder step D(399): virtual t=400 -> prev=0, cur=1
    if (blk >= 64) {
        int bd = blk - 64;
        lstm64(g_dWiT + (size_t)bd*1536*64,
               g_ah[0], RNN, g_ctx, ENC,
               g_dWhT + (size_t)bd*1024*64, g_dh[1],
               dB, bd*16, g_dc, g_dh[0],
               g_dhh + (size_t)(MELT-1)*RNN*BB, w_s, x_s);
    }
    gbar();

    // ================= epilogue: mel + gate projection =================
    for (int u = blk; u < MELT*2; u += NBLK) {
        int t = u >> 1, rz = u & 1;
        const int r = tid >> 3, b0 = (tid & 7) << 2, rg = rz*64 + r;
        float bv = (rg < NMEL) ? projB[rg] : ((rg == NMEL) ? gateB[0] : 0.f);
        float4 acc = make_float4(bv, bv, bv, bv);
        gemm64(acc, g_projT + (size_t)rz*1536*64,
               g_dhh + (size_t)t*RNN*BB, RNN, w_s, x_s);
        gemm64(acc, g_projT + ((size_t)rz*1536 + RNN)*64,
               g_ctxh + (size_t)t*ENC*BB, ENC, w_s, x_s);
        if (rg < NMEL) {
            out[((size_t)(b0 + 0)*NMEL + rg)*MELT + t] = acc.x;
            out[((size_t)(b0 + 1)*NMEL + rg)*MELT + t] = acc.y;
            out[((size_t)(b0 + 2)*NMEL + rg)*MELT + t] = acc.z;
            out[((size_t)(b0 + 3)*NMEL + rg)*MELT + t] = acc.w;
        } else if (rg == NMEL) {
            out[GATE_OFF + (size_t)(b0 + 0)*MELT + t] = acc.x;
            out[GATE_OFF + (size_t)(b0 + 1)*MELT + t] = acc.y;
            out[GATE_OFF + (size_t)(b0 + 2)*MELT + t] = acc.z;
            out[GATE_OFF + (size_t)(b0 + 3)*MELT + t] = acc.w;
        }
        __syncthreads();
    }
}

extern "C" void kernel_launch(void* const* d_in, const int* in_sizes, int n_in,
                              void* d_out, int out_size)
{
    decoder_all<<<NBLK, NTHR>>>(
        (const float*)d_in[0],  (const float*)d_in[1],  (const int*)d_in[2],
        (const float*)d_in[3],  (const float*)d_in[4],
        (const float*)d_in[5],  (const float*)d_in[6],  (const float*)d_in[7],
        (const float*)d_in[8],  (const float*)d_in[9],  (const float*)d_in[10],
        (const float*)d_in[11], (const float*)d_in[12],
        (const float*)d_in[13], (const float*)d_in[14], (const float*)d_in[15],
        (const float*)d_in[16], (const float*)d_in[17],
        (const float*)d_in[18], (const float*)d_in[19],
        (float*)d_out);
}

// round 16
// speedup vs baseline: 1.3832x; 1.2399x over previous
#include <cuda_runtime.h>
#include <math.h>

#define BB   32
#define TXT  256
#define MELT 400
#define ENC  512
#define NMEL 80
#define PRE  256
#define RNN  1024
#define AD   128
#define NBLK 128
#define NTHR 256
#define NEGV (-1e9f)

#define GATE_OFF  (BB*NMEL*MELT)
#define ALIGN_OFF (GATE_OFF + BB*MELT)

// ---------------- device-global scratch (allocation-free) ----------------
__device__ float g_x1  [(size_t)MELT*BB*PRE];    // [u=t*32+b][p]
__device__ float g_xpre[(size_t)MELT*PRE*BB];    // [t][k][b]
__device__ float g_pm  [(size_t)BB*TXT*AD];      // [b][tt][a]
__device__ float g_loc [(size_t)BB*TXT*AD];      // [b][tt][a]
__device__ float g_qWt [(size_t)RNN*AD];         // [k][a]
__device__ float g_ah  [2][RNN*BB];              // [k][b]
__device__ float g_ac  [RNN*BB];
__device__ float g_dh  [2][RNN*BB];
__device__ float g_dc  [RNN*BB];
__device__ float g_aw  [BB*TXT];
__device__ float g_awc [BB*TXT];
__device__ float g_ctx [ENC*BB];                 // [k][b]
__device__ float g_dhh [(size_t)MELT*RNN*BB];    // [t][k][b]
__device__ float g_ctxh[(size_t)MELT*ENC*BB];    // [t][k][b]
// pre-transposed weights: [tile][k][64 rows-in-tile]
__device__ float g_aWiT[(size_t)64*768*64];
__device__ float g_aWhT[(size_t)64*1024*64];
__device__ float g_dWiT[(size_t)64*1536*64];
__device__ float g_dWhT[(size_t)64*1024*64];
__device__ float g_projT[(size_t)2*1536*64];
__device__ unsigned g_barc;
__device__ unsigned g_barg;

__device__ __forceinline__ float sigm(float x) { return 1.0f/(1.0f+expf(-x)); }
__device__ __forceinline__ float tanha(float x) {
    float y; asm("tanh.approx.f32 %0, %1;" : "=f"(y) : "f"(x)); return y;
}

__device__ __forceinline__ void gbar() {
    __syncthreads();
    if (threadIdx.x == 0) {
        __threadfence();
        unsigned gen = *(volatile unsigned*)&g_barg;
        if (atomicAdd(&g_barc, 1u) == NBLK - 1u) {
            g_barc = 0u;
            __threadfence();
            *(volatile unsigned*)&g_barg = gen + 1u;
        } else {
            while (*(volatile unsigned*)&g_barg == gen) { __nanosleep(64); }
        }
        __threadfence();
    }
    __syncthreads();
}

// 64 rows x 32 batch GEMM, 256 threads, K-chunk 64, one sync per chunk.
// wT: [K][64] pre-transposed. X: [K][32]. K multiple of 64.
// thread: rows {2rp, 2rp+1} (rp=tid>>3), batches b0..b0+3 (b0=(tid&7)*4).
// SMEM layout: w_s = SMEM[0..8192) (2 x 4096), x_s = SMEM[8192..12288) (2 x 2048).
__device__ __forceinline__ void gemm64c(float4& A0, float4& A1,
    const float* __restrict__ wT, const float* __restrict__ X, int K,
    float* SMEM)
{
    float* w_s = SMEM;
    float* x_s = SMEM + 8192;
    const int tid = threadIdx.x;
    const int rp = tid >> 3, b0 = (tid & 7) << 2;
    const int nt = K >> 6;
    const float4* wg = (const float4*)wT;
    const float4* xg = (const float4*)X;
    float4 wv0 = wg[tid], wv1 = wg[256 + tid], wv2 = wg[512 + tid], wv3 = wg[768 + tid];
    float4 xv0 = __ldcg(xg + tid), xv1 = __ldcg(xg + 256 + tid);
    __syncthreads();                       // prior users of buffers done
    {
        float4* wsv = (float4*)w_s; float4* xsv = (float4*)x_s;
        wsv[tid] = wv0; wsv[256 + tid] = wv1; wsv[512 + tid] = wv2; wsv[768 + tid] = wv3;
        xsv[tid] = xv0; xsv[256 + tid] = xv1;
    }
    for (int c = 0; c < nt; c++) {
        const int cur = c & 1;
        if (c + 1 < nt) {
            const float4* wn = wg + (size_t)(c + 1)*1024;
            const float4* xn = xg + (size_t)(c + 1)*512;
            wv0 = wn[tid]; wv1 = wn[256 + tid]; wv2 = wn[512 + tid]; wv3 = wn[768 + tid];
            xv0 = __ldcg(xn + tid); xv1 = __ldcg(xn + 256 + tid);
        }
        __syncthreads();                   // staged chunk c visible
        const float* ws = w_s + cur*4096 + (rp << 1);
        const float* xs = x_s + cur*2048 + b0;
        #pragma unroll 16
        for (int k2 = 0; k2 < 64; k2++) {
            float2 w2 = *(const float2*)(ws + k2*64);     // LDS.64 broadcast
            float4 x4 = *(const float4*)(xs + k2*32);     // LDS.128, 128B/warp
            A0.x = fmaf(w2.x, x4.x, A0.x); A0.y = fmaf(w2.x, x4.y, A0.y);
            A0.z = fmaf(w2.x, x4.z, A0.z); A0.w = fmaf(w2.x, x4.w, A0.w);
            A1.x = fmaf(w2.y, x4.x, A1.x); A1.y = fmaf(w2.y, x4.y, A1.y);
            A1.z = fmaf(w2.y, x4.z, A1.z); A1.w = fmaf(w2.y, x4.w, A1.w);
        }
        if (c + 1 < nt) {                  // other buffer: its readers passed the sync
            const int nb = 1 - cur;
            float4* wsn = (float4*)(w_s + nb*4096);
            float4* xsn = (float4*)(x_s + nb*2048);
            wsn[tid] = wv0; wsn[256 + tid] = wv1; wsn[512 + tid] = wv2; wsn[768 + tid] = wv3;
            xsn[tid] = xv0; xsn[256 + tid] = xv1;
        }
    }
}

// one 64-gate-row tile (16 h-units x 4 gates) of an LSTM step
__device__ __forceinline__ void lstm64c(
    const float* __restrict__ wiT, const float* __restrict__ X1, int K1,
    const float* __restrict__ X2, int K2,
    const float* __restrict__ whT, const float* __restrict__ hprev,
    const float* __restrict__ bias, int u0,
    float* __restrict__ cst, float* __restrict__ hout, float* __restrict__ hist,
    float* SMEM)
{
    const int tid = threadIdx.x;
    const int rp = tid >> 3, b0 = (tid & 7) << 2;
    const int j0 = rp << 1, j1 = j0 + 1;
    float bv0 = bias[(j0 >> 4)*RNN + u0 + (j0 & 15)];
    float bv1 = bias[(j1 >> 4)*RNN + u0 + (j1 & 15)];
    float4 A0 = make_float4(bv0, bv0, bv0, bv0);
    float4 A1 = make_float4(bv1, bv1, bv1, bv1);
    gemm64c(A0, A1, wiT,                 X1,    K1,  SMEM);
    gemm64c(A0, A1, wiT + (size_t)K1*64, X2,    K2,  SMEM);
    gemm64c(A0, A1, whT,                 hprev, RNN, SMEM);
    float* x_s = SMEM + 8192;
    __syncthreads();
    *(float4*)(x_s + j0*32 + b0) = A0;
    *(float4*)(x_s + j1*32 + b0) = A1;
    __syncthreads();
    #pragma unroll
    for (int it = 0; it < 2; it++) {
        int idx = tid + it*256;
        int j = idx >> 5, b = idx & 31, h = u0 + j;
        float iv = x_s[(     j)*32 + b];
        float fv = x_s[(16 + j)*32 + b];
        float gv = x_s[(32 + j)*32 + b];
        float ov = x_s[(48 + j)*32 + b];
        float c  = sigm(fv)*cst[h*32 + b] + sigm(iv)*tanhf(gv);
        float hn = sigm(ov)*tanhf(c);
        cst[h*32 + b] = c;
        hout[h*32 + b] = hn;
        if (hist) hist[h*32 + b] = hn;
    }
    __syncthreads();
}

__global__ __launch_bounds__(NTHR, 1) void decoder_all(
    const float* __restrict__ memory, const float* __restrict__ din,
    const int* __restrict__ mlen,
    const float* __restrict__ preW1, const float* __restrict__ preW2,
    const float* __restrict__ aWi, const float* __restrict__ aWh,
    const float* __restrict__ aB,
    const float* __restrict__ convW, const float* __restrict__ denseW,
    const float* __restrict__ queryW, const float* __restrict__ memW,
    const float* __restrict__ vW,
    const float* __restrict__ dWi, const float* __restrict__ dWh,
    const float* __restrict__ dB,
    const float* __restrict__ projW, const float* __restrict__ projB,
    const float* __restrict__ gateW, const float* __restrict__ gateB,
    float* __restrict__ out)
{
    __shared__ __align__(16) float SMEM[12288];   // 48KB overlay
    const int blk = blockIdx.x, tid = threadIdx.x;
    const int gt = blk*NTHR + tid;                // 0..32767

    // ================= prologue =================
    {   // zero recurrent state (NBLK*NTHR == RNN*BB exactly)
        int i = gt;
        g_ah[0][i] = 0.f; g_ah[1][i] = 0.f; g_ac[i] = 0.f;
        g_dh[0][i] = 0.f; g_dh[1][i] = 0.f; g_dc[i] = 0.f;
        if (i < BB*TXT) { g_aw[i] = 0.f; g_awc[i] = 0.f; }
        if (i < ENC*BB) g_ctx[i] = 0.f;
    }
    for (int i = gt; i < RNN*AD; i += NBLK*NTHR)
        g_qWt[i] = queryW[(size_t)(i & 127)*RNN + (i >> 7)];
    // weight transposes into [tile][k][64]
    {
        const size_t nA = (size_t)64*64*768;
        for (size_t i = gt; i < nA; i += NBLK*NTHR) {
            int k = (int)(i % 768); size_t rem = i / 768;
            int j = (int)(rem & 63); int tile = (int)(rem >> 6);
            int rg = (j >> 4)*RNN + tile*16 + (j & 15);
            g_aWiT[((size_t)tile*768 + k)*64 + j] = aWi[(size_t)rg*768 + k];
        }
        const size_t nH = (size_t)64*64*1024;
        for (size_t i = gt; i < nH; i += NBLK*NTHR) {
            int k = (int)(i & 1023); size_t rem = i >> 10;
            int j = (int)(rem & 63); int tile = (int)(rem >> 6);
            int rg = (j >> 4)*RNN + tile*16 + (j & 15);
            g_aWhT[((size_t)tile*1024 + k)*64 + j] = aWh[(size_t)rg*1024 + k];
            g_dWhT[((size_t)tile*1024 + k)*64 + j] = dWh[(size_t)rg*1024 + k];
        }
        const size_t nD = (size_t)64*64*1536;
        for (size_t i = gt; i < nD; i += NBLK*NTHR) {
            int k = (int)(i % 1536); size_t rem = i / 1536;
            int j = (int)(rem & 63); int tile = (int)(rem >> 6);
            int rg = (j >> 4)*RNN + tile*16 + (j & 15);
            g_dWiT[((size_t)tile*1536 + k)*64 + j] = dWi[(size_t)rg*1536 + k];
        }
        const size_t nP = (size_t)2*64*1536;
        for (size_t i = gt; i < nP; i += NBLK*NTHR) {
            int k = (int)(i % 1536); size_t rem = i / 1536;
            int j = (int)(rem & 63); int rz = (int)(rem >> 6);
            int rr = rz*64 + j;
            float v = 0.f;
            if (rr < NMEL)       v = projW[(size_t)rr*1536 + k];
            else if (rr == NMEL) v = gateW[k];
            g_projT[((size_t)rz*1536 + k)*64 + j] = v;
        }
    }
    // prenet layer 1: one (t,b) unit per block-iteration
    for (int u = blk; u < MELT*BB; u += NBLK) {
        int t = u >> 5, b = u & 31;
        __syncthreads();
        if (tid < NMEL)
            SMEM[tid] = (t == 0) ? 0.f : din[((size_t)(b*NMEL + tid))*MELT + t - 1];
        __syncthreads();
        float s = 0.f;
        const float* w = preW1 + (size_t)tid*NMEL;
        #pragma unroll
        for (int m = 0; m < NMEL; m++) s = fmaf(SMEM[m], w[m], s);
        g_x1[(size_t)u*PRE + tid] = fmaxf(s, 0.f);
    }
    // prenet layer 2 (writes [t][k][b])
    for (int u = blk; u < MELT*BB; u += NBLK) {
        int t = u >> 5, b = u & 31;
        __syncthreads();
        SMEM[tid] = g_x1[(size_t)u*PRE + tid];   // written by this block above
        __syncthreads();
        float s = 0.f;
        const float* w = preW2 + (size_t)tid*PRE;
        #pragma unroll 8
        for (int k = 0; k < PRE; k++) s = fmaf(SMEM[k], w[k], s);
        g_xpre[((size_t)t*PRE + tid)*BB + b] = fmaxf(s, 0.f);
    }
    // processed memory: unit = (b, 2 tt rows)
    for (int u = blk; u < BB*128; u += NBLK) {
        int b = u >> 7, t2 = (u & 127) << 1;
        __syncthreads();
        for (int i = tid; i < 2*ENC; i += NTHR)
            SMEM[i] = memory[((size_t)(b*TXT + t2))*ENC + i];
        __syncthreads();
        int a = tid & 127, tl = tid >> 7;
        float s = 0.f;
        const float* w = memW + (size_t)a*ENC;
        const float* xr = SMEM + tl*ENC;
        #pragma unroll 8
        for (int e = 0; e < ENC; e++) s = fmaf(xr[e], w[e], s);
        g_pm[((size_t)(b*TXT + t2 + tl))*AD + a] = s;
    }
    gbar();

    // ================= 400-step sequential loop =================
    for (int t = 0; t < MELT; t++) {
        const int prev = t & 1, cur = prev ^ 1;

        // ---- interval 1: A(t)+conv on blocks 0-63 || D(t-1) on blocks 64-127 ----
        if (blk < 64) {
            lstm64c(g_aWiT + (size_t)blk*768*64,
                    g_xpre + (size_t)t*PRE*BB, PRE, g_ctx, ENC,
                    g_aWhT + (size_t)blk*1024*64, g_ah[prev],
                    aB, blk*16, g_ac, g_ah[cur], (float*)0, SMEM);
            // location conv + dense: 4 units per block (covers all 256)
            float* work = SMEM;            // a0:64 a1:64 fs:1056
            float* cw   = SMEM + 6144;     // 1984
            float* dW   = SMEM + 2048;     // 4096 [nf][128]
            for (int i = tid; i < 1984; i += NTHR) cw[i] = convW[i];
            for (int i = tid; i < 4096; i += NTHR) {
                int nf = i >> 7, a = i & 127;
                dW[i] = denseW[a*32 + nf];
            }
            float* a0 = work, *a1 = work + 64, *fs = work + 128;
            for (int qq = 0; qq < 4; qq++) {
                int unit = blk*4 + qq;
                int b2 = unit >> 3, tth = (unit & 7) << 5;
                __syncthreads();
                if (tid < 62) {
                    int idx = tth - 15 + tid;
                    bool ok = (idx >= 0 && idx < TXT);
                    a0[tid] = ok ? __ldcg(&g_aw [b2*TXT + idx]) : 0.f;
                    a1[tid] = ok ? __ldcg(&g_awc[b2*TXT + idx]) : 0.f;
                }
                __syncthreads();
                {
                    int ttl = tid & 31;
                    #pragma unroll
                    for (int q2 = 0; q2 < 4; q2++) {
                        int nf = (tid >> 5) + q2*8;
                        const float* c0 = cw + nf*62;
                        float s = 0.f;
                        #pragma unroll
                        for (int k = 0; k < 31; k++)
                            s += c0[k]*a0[ttl + k] + c0[31 + k]*a1[ttl + k];
                        fs[nf*33 + ttl] = s;
                    }
                }
                __syncthreads();
                {
                    int a = tid & 127, hf = tid >> 7;
                    float wr[32];
                    #pragma unroll
                    for (int nf = 0; nf < 32; nf++) wr[nf] = dW[nf*128 + a];
                    #pragma unroll
                    for (int tl = 0; tl < 16; tl++) {
                        int ttl = hf*16 + tl;
                        float s = 0.f;
                        #pragma unroll
                        for (int nf = 0; nf < 32; nf++)
                            s = fmaf(wr[nf], fs[nf*33 + ttl], s);
                        g_loc[((size_t)(b2*TXT + tth + ttl))*AD + a] = s;
                    }
                }
                __syncthreads();
            }
        } else if (t > 0) {
            int bd = blk - 64;
            lstm64c(g_dWiT + (size_t)bd*1536*64,
                    g_ah[prev], RNN, g_ctx, ENC,
                    g_dWhT + (size_t)bd*1024*64, g_dh[cur],
                    dB, bd*16, g_dc, g_dh[prev],
                    g_dhh + (size_t)(t-1)*RNN*BB, SMEM);
        }
        gbar();

        // ---- interval 2: attention (blocks 0..31, one per batch) ----
        if (blk < BB) {
            const int b = blk;
            float* ah_s = SMEM;                 // 1024
            float* q_s  = SMEM + 1024;          // 128
            float* v_s  = SMEM + 1152;          // 128
            float* red  = SMEM + 1280;          // 256
            float* aw_s = SMEM + 1536;          // 256
            const float* ahp = g_ah[cur];
            for (int k = tid; k < RNN; k += NTHR) ah_s[k] = __ldcg(ahp + k*32 + b);
            if (tid < AD) v_s[tid] = vW[tid];
            __syncthreads();
            {   // query projection: 2 halves x 128 a
                int a = tid & 127, qr = tid >> 7;
                float s = 0.f;
                const float* qw = g_qWt + (size_t)qr*512*AD + a;
                const float* ar = ah_s + qr*512;
                #pragma unroll 8
                for (int k = 0; k < 512; k++) s = fmaf(qw[(size_t)k*AD], ar[k], s);
                red[tid] = s;
                __syncthreads();
                if (tid < 128) q_s[tid] = red[tid] + red[128 + tid];
            }
            __syncthreads();
            float e;
            {
                const float4* lp = (const float4*)(g_loc + ((size_t)(b*TXT + tid))*AD);
                const float4* pp = (const float4*)(g_pm  + ((size_t)(b*TXT + tid))*AD);
                const float4* qp = (const float4*)q_s;
                const float4* vp = (const float4*)v_s;
                float ee = 0.f;
                #pragma unroll 8
                for (int i = 0; i < 32; i++) {
                    float4 l = __ldcg(lp + i), p = pp[i], qv = qp[i], vv = vp[i];
                    ee = fmaf(vv.x, tanha(l.x + qv.x + p.x), ee);
                    ee = fmaf(vv.y, tanha(l.y + qv.y + p.y), ee);
                    ee = fmaf(vv.z, tanha(l.z + qv.z + p.z), ee);
                    ee = fmaf(vv.w, tanha(l.w + qv.w + p.w), ee);
                }
                e = (tid >= mlen[b]) ? NEGV : ee;
            }
            red[tid] = e; __syncthreads();
            for (int s2 = 128; s2 > 0; s2 >>= 1) {
                if (tid < s2) red[tid] = fmaxf(red[tid], red[tid + s2]);
                __syncthreads();
            }
            float mx = red[0]; __syncthreads();
            float ex = expf(e - mx);
            red[tid] = ex; __syncthreads();
            for (int s2 = 128; s2 > 0; s2 >>= 1) {
                if (tid < s2) red[tid] += red[tid + s2];
                __syncthreads();
            }
            float inv = 1.0f / red[0];
            {
                float aw = ex * inv;
                aw_s[tid] = aw;
                g_aw[b*TXT + tid] = aw;
                g_awc[b*TXT + tid] = __ldcg(&g_awc[b*TXT + tid]) + aw;
                out[ALIGN_OFF + ((size_t)b*MELT + t)*TXT + tid] = aw;
            }
            __syncthreads();
            {   // context: 2 ENC elements per thread
                #pragma unroll
                for (int it = 0; it < 2; it++) {
                    int e2 = tid + it*256;
                    const float* mb = memory + (size_t)b*TXT*ENC + e2;
                    float cx = 0.f;
                    #pragma unroll 8
                    for (int k = 0; k < TXT; k++)
                        cx = fmaf(aw_s[k], mb[(size_t)k*ENC], cx);
                    g_ctx[e2*32 + b] = cx;
                    g_ctxh[((size_t)t*ENC + e2)*32 + b] = cx;
                }
            }
            __syncthreads();
        }
        gbar();
    }

    // final decoder step D(399): virtual t=400 -> prev=0, cur=1
    if (blk >= 64) {
        int bd = blk - 64;
        lstm64c(g_dWiT + (size_t)bd*1536*64,
                g_ah[0], RNN, g_ctx, ENC,
                g_dWhT + (size_t)bd*1024*64, g_dh[1],
                dB, bd*16, g_dc, g_dh[0],
                g_dhh + (size_t)(MELT-1)*RNN*BB, SMEM);
    }
    gbar();

    // ================= epilogue: mel + gate projection =================
    for (int u = blk; u < MELT*2; u += NBLK) {
        int t = u >> 1, rz = u & 1;
        const int rp = tid >> 3, b0 = (tid & 7) << 2;
        const int j0 = rp << 1, j1 = j0 + 1;
        const int rg0 = rz*64 + j0, rg1 = rz*64 + j1;
        float bv0 = (rg0 < NMEL) ? projB[rg0] : ((rg0 == NMEL) ? gateB[0] : 0.f);
        float bv1 = (rg1 < NMEL) ? projB[rg1] : ((rg1 == NMEL) ? gateB[0] : 0.f);
        float4 A0 = make_float4(bv0, bv0, bv0, bv0);
        float4 A1 = make_float4(bv1, bv1, bv1, bv1);
        gemm64c(A0, A1, g_projT + (size_t)rz*1536*64,
                g_dhh + (size_t)t*RNN*BB, RNN, SMEM);
        gemm64c(A0, A1, g_projT + ((size_t)rz*1536 + RNN)*64,
                g_ctxh + (size_t)t*ENC*BB, ENC, SMEM);
        if (rg0 < NMEL) {
            out[((size_t)(b0 + 0)*NMEL + rg0)*MELT + t] = A0.x;
            out[((size_t)(b0 + 1)*NMEL + rg0)*MELT + t] = A0.y;
            out[((size_t)(b0 + 2)*NMEL + rg0)*MELT + t] = A0.z;
            out[((size_t)(b0 + 3)*NMEL + rg0)*MELT + t] = A0.w;
        } else if (rg0 == NMEL) {
            out[GATE_OFF + (size_t)(b0 + 0)*MELT + t] = A0.x;
            out[GATE_OFF + (size_t)(b0 + 1)*MELT + t] = A0.y;
            out[GATE_OFF + (size_t)(b0 + 2)*MELT + t] = A0.z;
            out[GATE_OFF + (size_t)(b0 + 3)*MELT + t] = A0.w;
        }
        if (rg1 < NMEL) {
            out[((size_t)(b0 + 0)*NMEL + rg1)*MELT + t] = A1.x;
            out[((size_t)(b0 + 1)*NMEL + rg1)*MELT + t] = A1.y;
            out[((size_t)(b0 + 2)*NMEL + rg1)*MELT + t] = A1.z;
            out[((size_t)(b0 + 3)*NMEL + rg1)*MELT + t] = A1.w;
        } else if (rg1 == NMEL) {
            out[GATE_OFF + (size_t)(b0 + 0)*MELT + t] = A1.x;
            out[GATE_OFF + (size_t)(b0 + 1)*MELT + t] = A1.y;
            out[GATE_OFF + (size_t)(b0 + 2)*MELT + t] = A1.z;
            out[GATE_OFF + (size_t)(b0 + 3)*MELT + t] = A1.w;
        }
        __syncthreads();
    }
}

extern "C" void kernel_launch(void* const* d_in, const int* in_sizes, int n_in,
                              void* d_out, int out_size)
{
    decoder_all<<<NBLK, NTHR>>>(
        (const float*)d_in[0],  (const float*)d_in[1],  (const int*)d_in[2],
        (const float*)d_in[3],  (const float*)d_in[4],
        (const float*)d_in[5],  (const float*)d_in[6],  (const float*)d_in[7],
        (const float*)d_in[8],  (const float*)d_in[9],  (const float*)d_in[10],
        (const float*)d_in[11], (const float*)d_in[12],
        (const float*)d_in[13], (const float*)d_in[14], (const float*)d_in[15],
        (const float*)d_in[16], (const float*)d_in[17],
        (const float*)d_in[18], (const float*)d_in[19],
        (float*)d_out);
}

// round 17
// speedup vs baseline: 1.6279x; 1.1769x over previous
#include <cuda_runtime.h>
#include <math.h>

#define BB   32
#define TXT  256
#define MELT 400
#define ENC  512
#define NMEL 80
#define PRE  256
#define RNN  1024
#define AD   128
#define NBLK 128
#define NTHR 512
#define NEGV (-1e9f)

#define GATE_OFF  (BB*NMEL*MELT)
#define ALIGN_OFF (GATE_OFF + BB*MELT)

// ---------------- device-global scratch (allocation-free) ----------------
__device__ float g_x1  [(size_t)MELT*BB*PRE];    // [u=t*32+b][p]
__device__ float g_xpre[(size_t)MELT*PRE*BB];    // [t][k][b]
__device__ float g_pm  [(size_t)BB*TXT*AD];      // [b][tt][a]
__device__ float g_loc [(size_t)BB*TXT*AD];      // [b][tt][a]
__device__ float g_qWt [(size_t)RNN*AD];         // [k][a]
__device__ float g_ah  [2][RNN*BB];              // [k][b]
__device__ float g_ac  [RNN*BB];
__device__ float g_dh  [2][RNN*BB];
__device__ float g_dc  [RNN*BB];
__device__ float g_aw  [BB*TXT];
__device__ float g_awc [BB*TXT];
__device__ float g_ctx [ENC*BB];                 // [k][b]
__device__ float g_dhh [(size_t)MELT*RNN*BB];    // [t][k][b]
__device__ float g_ctxh[(size_t)MELT*ENC*BB];    // [t][k][b]
// pre-transposed weights: [tile][k][64 rows-in-tile]
__device__ float g_aWiT[(size_t)64*768*64];
__device__ float g_aWhT[(size_t)64*1024*64];
__device__ float g_dWiT[(size_t)64*1536*64];
__device__ float g_dWhT[(size_t)64*1024*64];
__device__ float g_projT[(size_t)2*1536*64];
__device__ unsigned g_barc;
__device__ unsigned g_barg;

__device__ __forceinline__ float sigm(float x) { return 1.0f/(1.0f+expf(-x)); }
__device__ __forceinline__ float tanha(float x) {
    float y; asm("tanh.approx.f32 %0, %1;" : "=f"(y) : "f"(x)); return y;
}

__device__ __forceinline__ void gbar() {
    __syncthreads();
    if (threadIdx.x == 0) {
        __threadfence();
        unsigned gen = *(volatile unsigned*)&g_barg;
        if (atomicAdd(&g_barc, 1u) == NBLK - 1u) {
            g_barc = 0u;
            __threadfence();
            *(volatile unsigned*)&g_barg = gen + 1u;
        } else {
            while (*(volatile unsigned*)&g_barg == gen) { __nanosleep(64); }
        }
        __threadfence();
    }
    __syncthreads();
}

// 64 rows x 32 batch GEMM, 512 threads, K-chunk 64, one sync per chunk.
// wT: [K][64] pre-transposed. X: [K][32]. K multiple of 64.
// thread: rows {rp2, rp2+1} (rp2=(tid>>4)*2), batches {bp, bp+1} (bp=(tid&15)*2).
// SMEM: w_s = SMEM[0..8192) (2 x 4096), x_s = SMEM[8192..12288) (2 x 2048).
__device__ __forceinline__ void gemm64c(float2& A0, float2& A1,
    const float* __restrict__ wT, const float* __restrict__ X, int K,
    float* SMEM)
{
    float* w_s = SMEM;
    float* x_s = SMEM + 8192;
    const int tid = threadIdx.x;
    const int rp2 = (tid >> 4) << 1, bp = (tid & 15) << 1;
    const int nt = K >> 6;
    const float4* wg = (const float4*)wT;
    const float4* xg = (const float4*)X;
    float4 wv0 = wg[tid], wv1 = wg[512 + tid];
    float4 xv0 = __ldcg(xg + tid);
    __syncthreads();                       // prior users of buffers done
    ((float4*)w_s)[tid] = wv0; ((float4*)w_s)[512 + tid] = wv1;
    ((float4*)x_s)[tid] = xv0;
    for (int c = 0; c < nt; c++) {
        const int cur = c & 1;
        if (c + 1 < nt) {
            const float4* wn = wg + (size_t)(c + 1)*1024;
            wv0 = wn[tid]; wv1 = wn[512 + tid];
            xv0 = __ldcg(xg + (size_t)(c + 1)*512 + tid);
        }
        __syncthreads();                   // staged chunk c visible
        const float* ws = w_s + cur*4096 + rp2;
        const float* xs = x_s + cur*2048 + bp;
        #pragma unroll 8
        for (int k2 = 0; k2 < 64; k2++) {
            float2 w2 = *(const float2*)(ws + k2*64);   // 2-addr broadcast
            float2 x2 = *(const float2*)(xs + k2*32);   // 128B contiguous/warp
            A0.x = fmaf(w2.x, x2.x, A0.x); A0.y = fmaf(w2.x, x2.y, A0.y);
            A1.x = fmaf(w2.y, x2.x, A1.x); A1.y = fmaf(w2.y, x2.y, A1.y);
        }
        if (c + 1 < nt) {                  // other buffer: readers passed sync
            const int nb = 1 - cur;
            ((float4*)(w_s + nb*4096))[tid] = wv0;
            ((float4*)(w_s + nb*4096))[512 + tid] = wv1;
            ((float4*)(x_s + nb*2048))[tid] = xv0;
        }
    }
}

// one 64-gate-row tile (16 h-units x 4 gates) of an LSTM step
__device__ __forceinline__ void lstm64c(
    const float* __restrict__ wiT, const float* __restrict__ X1, int K1,
    const float* __restrict__ X2, int K2,
    const float* __restrict__ whT, const float* __restrict__ hprev,
    const float* __restrict__ bias, int u0,
    float* __restrict__ cst, float* __restrict__ hout, float* __restrict__ hist,
    float* SMEM)
{
    const int tid = threadIdx.x;
    const int rp2 = (tid >> 4) << 1, bp = (tid & 15) << 1;
    const int j0 = rp2, j1 = rp2 + 1;
    float bv0 = bias[(j0 >> 4)*RNN + u0 + (j0 & 15)];
    float bv1 = bias[(j1 >> 4)*RNN + u0 + (j1 & 15)];
    float2 A0 = make_float2(bv0, bv0);
    float2 A1 = make_float2(bv1, bv1);
    gemm64c(A0, A1, wiT,                 X1,    K1,  SMEM);
    gemm64c(A0, A1, wiT + (size_t)K1*64, X2,    K2,  SMEM);
    gemm64c(A0, A1, whT,                 hprev, RNN, SMEM);
    float* x_s = SMEM + 8192;
    __syncthreads();
    *(float2*)(x_s + j0*32 + bp) = A0;
    *(float2*)(x_s + j1*32 + bp) = A1;
    __syncthreads();
    {
        int j = tid >> 5, b = tid & 31, h = u0 + j;   // 16 units x 32 batch
        float iv = x_s[(     j)*32 + b];
        float fv = x_s[(16 + j)*32 + b];
        float gv = x_s[(32 + j)*32 + b];
        float ov = x_s[(48 + j)*32 + b];
        float c  = sigm(fv)*cst[h*32 + b] + sigm(iv)*tanhf(gv);
        float hn = sigm(ov)*tanhf(c);
        cst[h*32 + b] = c;
        hout[h*32 + b] = hn;
        if (hist) hist[h*32 + b] = hn;
    }
    __syncthreads();
}

__global__ __launch_bounds__(NTHR, 1) void decoder_all(
    const float* __restrict__ memory, const float* __restrict__ din,
    const int* __restrict__ mlen,
    const float* __restrict__ preW1, const float* __restrict__ preW2,
    const float* __restrict__ aWi, const float* __restrict__ aWh,
    const float* __restrict__ aB,
    const float* __restrict__ convW, const float* __restrict__ denseW,
    const float* __restrict__ queryW, const float* __restrict__ memW,
    const float* __restrict__ vW,
    const float* __restrict__ dWi, const float* __restrict__ dWh,
    const float* __restrict__ dB,
    const float* __restrict__ projW, const float* __restrict__ projB,
    const float* __restrict__ gateW, const float* __restrict__ gateB,
    float* __restrict__ out)
{
    __shared__ __align__(16) float SMEM[12288];   // 48KB overlay
    const int blk = blockIdx.x, tid = threadIdx.x;
    const int gt = blk*NTHR + tid;                // 0..65535

    // ================= prologue =================
    for (int i = gt; i < RNN*BB; i += NBLK*NTHR) {
        g_ah[0][i] = 0.f; g_ah[1][i] = 0.f; g_ac[i] = 0.f;
        g_dh[0][i] = 0.f; g_dh[1][i] = 0.f; g_dc[i] = 0.f;
        if (i < BB*TXT) { g_aw[i] = 0.f; g_awc[i] = 0.f; }
        if (i < ENC*BB) g_ctx[i] = 0.f;
    }
    for (int i = gt; i < RNN*AD; i += NBLK*NTHR)
        g_qWt[i] = queryW[(size_t)(i & 127)*RNN + (i >> 7)];
    // weight transposes into [tile][k][64]
    {
        const size_t nA = (size_t)64*64*768;
        for (size_t i = gt; i < nA; i += NBLK*NTHR) {
            int k = (int)(i % 768); size_t rem = i / 768;
            int j = (int)(rem & 63); int tile = (int)(rem >> 6);
            int rg = (j >> 4)*RNN + tile*16 + (j & 15);
            g_aWiT[((size_t)tile*768 + k)*64 + j] = aWi[(size_t)rg*768 + k];
        }
        const size_t nH = (size_t)64*64*1024;
        for (size_t i = gt; i < nH; i += NBLK*NTHR) {
            int k = (int)(i & 1023); size_t rem = i >> 10;
            int j = (int)(rem & 63); int tile = (int)(rem >> 6);
            int rg = (j >> 4)*RNN + tile*16 + (j & 15);
            g_aWhT[((size_t)tile*1024 + k)*64 + j] = aWh[(size_t)rg*1024 + k];
            g_dWhT[((size_t)tile*1024 + k)*64 + j] = dWh[(size_t)rg*1024 + k];
        }
        const size_t nD = (size_t)64*64*1536;
        for (size_t i = gt; i < nD; i += NBLK*NTHR) {
            int k = (int)(i % 1536); size_t rem = i / 1536;
            int j = (int)(rem & 63); int tile = (int)(rem >> 6);
            int rg = (j >> 4)*RNN + tile*16 + (j & 15);
            g_dWiT[((size_t)tile*1536 + k)*64 + j] = dWi[(size_t)rg*1536 + k];
        }
        const size_t nP = (size_t)2*64*1536;
        for (size_t i = gt; i < nP; i += NBLK*NTHR) {
            int k = (int)(i % 1536); size_t rem = i / 1536;
            int j = (int)(rem & 63); int rz = (int)(rem >> 6);
            int rr = rz*64 + j;
            float v = 0.f;
            if (rr < NMEL)       v = projW[(size_t)rr*1536 + k];
            else if (rr == NMEL) v = gateW[k];
            g_projT[((size_t)rz*1536 + k)*64 + j] = v;
        }
    }
    // prenet layer 1: two (t,b) units per block-iteration
    for (int u0 = blk*2; u0 < MELT*BB; u0 += NBLK*2) {
        int half = tid >> 8, tid2 = tid & 255;
        int u = u0 + half, t = u >> 5, b = u & 31;
        float* fr = SMEM + half*1024;
        __syncthreads();
        if (tid2 < NMEL)
            fr[tid2] = (t == 0) ? 0.f : din[((size_t)(b*NMEL + tid2))*MELT + t - 1];
        __syncthreads();
        float s = 0.f;
        const float* w = preW1 + (size_t)tid2*NMEL;
        #pragma unroll
        for (int m = 0; m < NMEL; m++) s = fmaf(fr[m], w[m], s);
        g_x1[(size_t)u*PRE + tid2] = fmaxf(s, 0.f);
    }
    // prenet layer 2 (writes [t][k][b])
    for (int u0 = blk*2; u0 < MELT*BB; u0 += NBLK*2) {
        int half = tid >> 8, tid2 = tid & 255;
        int u = u0 + half, t = u >> 5, b = u & 31;
        float* xr = SMEM + half*1024;
        __syncthreads();
        xr[tid2] = g_x1[(size_t)u*PRE + tid2];   // written by this block above
        __syncthreads();
        float s = 0.f;
        const float* w = preW2 + (size_t)tid2*PRE;
        #pragma unroll 8
        for (int k = 0; k < PRE; k++) s = fmaf(xr[k], w[k], s);
        g_xpre[((size_t)t*PRE + tid2)*BB + b] = fmaxf(s, 0.f);
    }
    // processed memory: unit = (b, 4 tt rows)
    for (int u = blk; u < BB*64; u += NBLK) {
        int b = u >> 6, tt4 = (u & 63) << 2;
        __syncthreads();
        for (int i = tid; i < 4*ENC; i += NTHR)
            SMEM[i] = memory[((size_t)(b*TXT + tt4))*ENC + i];
        __syncthreads();
        int a = tid & 127, tl = tid >> 7;
        float s = 0.f;
        const float* w = memW + (size_t)a*ENC;
        const float* xr = SMEM + tl*ENC;
        #pragma unroll 8
        for (int e = 0; e < ENC; e++) s = fmaf(xr[e], w[e], s);
        g_pm[((size_t)(b*TXT + tt4 + tl))*AD + a] = s;
    }
    gbar();

    // ================= 400-step sequential loop =================
    for (int t = 0; t < MELT; t++) {
        const int prev = t & 1, cur = prev ^ 1;

        // ---- interval 1: A(t)+conv on blocks 0-63 || D(t-1) on blocks 64-127 ----
        if (blk < 64) {
            lstm64c(g_aWiT + (size_t)blk*768*64,
                    g_xpre + (size_t)t*PRE*BB, PRE, g_ctx, ENC,
                    g_aWhT + (size_t)blk*1024*64, g_ah[prev],
                    aB, blk*16, g_ac, g_ah[cur], (float*)0, SMEM);
            // location conv + dense: 4 units per block (covers all 256)
            float* work = SMEM;            // a0:64 a1:64 fs:1056
            float* dW   = SMEM + 2048;     // 4096 [nf][128]
            float* cw   = SMEM + 6144;     // 1984
            for (int i = tid; i < 1984; i += NTHR) cw[i] = convW[i];
            for (int i = tid; i < 4096; i += NTHR) {
                int nf = i >> 7, a = i & 127;
                dW[i] = denseW[a*32 + nf];
            }
            float* a0 = work, *a1 = work + 64, *fs = work + 128;
            for (int qq = 0; qq < 4; qq++) {
                int unit = blk*4 + qq;
                int b2 = unit >> 3, tth = (unit & 7) << 5;
                __syncthreads();
                if (tid < 62) {
                    int idx = tth - 15 + tid;
                    bool ok = (idx >= 0 && idx < TXT);
                    a0[tid] = ok ? __ldcg(&g_aw [b2*TXT + idx]) : 0.f;
                    a1[tid] = ok ? __ldcg(&g_awc[b2*TXT + idx]) : 0.f;
                }
                __syncthreads();
                {
                    int ttl = tid & 31;
                    #pragma unroll
                    for (int q2 = 0; q2 < 2; q2++) {
                        int nf = (tid >> 5) + (q2 << 4);
                        const float* c0 = cw + nf*62;
                        float s = 0.f;
                        #pragma unroll
                        for (int k = 0; k < 31; k++)
                            s += c0[k]*a0[ttl + k] + c0[31 + k]*a1[ttl + k];
                        fs[nf*33 + ttl] = s;
                    }
                }
                __syncthreads();
                {
                    int a = tid & 127, qf = tid >> 7;
                    float wr[32];
                    #pragma unroll
                    for (int nf = 0; nf < 32; nf++) wr[nf] = dW[nf*128 + a];
                    #pragma unroll
                    for (int tl = 0; tl < 8; tl++) {
                        int ttl = qf*8 + tl;
                        float s = 0.f;
                        #pragma unroll
                        for (int nf = 0; nf < 32; nf++)
                            s = fmaf(wr[nf], fs[nf*33 + ttl], s);
                        g_loc[((size_t)(b2*TXT + tth + ttl))*AD + a] = s;
                    }
                }
                __syncthreads();
            }
        } else if (t > 0) {
            int bd = blk - 64;
            lstm64c(g_dWiT + (size_t)bd*1536*64,
                    g_ah[prev], RNN, g_ctx, ENC,
                    g_dWhT + (size_t)bd*1024*64, g_dh[cur],
                    dB, bd*16, g_dc, g_dh[prev],
                    g_dhh + (size_t)(t-1)*RNN*BB, SMEM);
        }
        gbar();

        // ---- interval 2: attention (blocks 0..31, one per batch) ----
        if (blk < BB) {
            const int b = blk;
            float* ah_s = SMEM;                 // 1024
            float* q_s  = SMEM + 1024;          // 128
            float* v_s  = SMEM + 1152;          // 128
            float* red  = SMEM + 1280;          // 512
            float* aw_s = SMEM + 1792;          // 256
            const float* ahp = g_ah[cur];
            for (int k = tid; k < RNN; k += NTHR) ah_s[k] = __ldcg(ahp + k*32 + b);
            if (tid < AD) v_s[tid] = vW[tid];
            __syncthreads();
            {   // query projection: 4 quarters x 128 a
                int a = tid & 127, qr = tid >> 7;
                float s = 0.f;
                const float* qw = g_qWt + (size_t)qr*256*AD + a;
                const float* ar = ah_s + qr*256;
                #pragma unroll 8
                for (int k = 0; k < 256; k++) s = fmaf(qw[(size_t)k*AD], ar[k], s);
                red[tid] = s;
                __syncthreads();
                if (tid < 128)
                    q_s[tid] = red[tid] + red[128 + tid] + red[256 + tid] + red[384 + tid];
            }
            __syncthreads();
            float e = NEGV;
            if (tid < TXT) {
                const float4* lp = (const float4*)(g_loc + ((size_t)(b*TXT + tid))*AD);
                const float4* pp = (const float4*)(g_pm  + ((size_t)(b*TXT + tid))*AD);
                const float4* qp = (const float4*)q_s;
                const float4* vp = (const float4*)v_s;
                float ee = 0.f;
                #pragma unroll 8
                for (int i = 0; i < 32; i++) {
                    float4 l = __ldcg(lp + i), p = pp[i], qv = qp[i], vv = vp[i];
                    ee = fmaf(vv.x, tanha(l.x + qv.x + p.x), ee);
                    ee = fmaf(vv.y, tanha(l.y + qv.y + p.y), ee);
                    ee = fmaf(vv.z, tanha(l.z + qv.z + p.z), ee);
                    ee = fmaf(vv.w, tanha(l.w + qv.w + p.w), ee);
                }
                e = (tid >= mlen[b]) ? NEGV : ee;
            }
            red[tid] = e; __syncthreads();
            for (int s2 = 256; s2 > 0; s2 >>= 1) {
                if (tid < s2) red[tid] = fmaxf(red[tid], red[tid + s2]);
                __syncthreads();
            }
            float mx = red[0]; __syncthreads();
            float ex = (tid < TXT) ? expf(e - mx) : 0.f;
            red[tid] = ex; __syncthreads();
            for (int s2 = 256; s2 > 0; s2 >>= 1) {
                if (tid < s2) red[tid] += red[tid + s2];
                __syncthreads();
            }
            float inv = 1.0f / red[0];
            if (tid < TXT) {
                float aw = ex * inv;
                aw_s[tid] = aw;
                g_aw[b*TXT + tid] = aw;
                g_awc[b*TXT + tid] = __ldcg(&g_awc[b*TXT + tid]) + aw;
                out[ALIGN_OFF + ((size_t)b*MELT + t)*TXT + tid] = aw;
            }
            __syncthreads();
            {   // context: one ENC element per thread (ENC == NTHR)
                int e2 = tid;
                const float* mb = memory + (size_t)b*TXT*ENC + e2;
                float cx = 0.f;
                #pragma unroll 8
                for (int k = 0; k < TXT; k++)
                    cx = fmaf(aw_s[k], mb[(size_t)k*ENC], cx);
                g_ctx[e2*32 + b] = cx;
                g_ctxh[((size_t)t*ENC + e2)*32 + b] = cx;
            }
            __syncthreads();
        }
        gbar();
    }

    // final decoder step D(399): virtual t=400 -> prev=0, cur=1
    if (blk >= 64) {
        int bd = blk - 64;
        lstm64c(g_dWiT + (size_t)bd*1536*64,
                g_ah[0], RNN, g_ctx, ENC,
                g_dWhT + (size_t)bd*1024*64, g_dh[1],
                dB, bd*16, g_dc, g_dh[0],
                g_dhh + (size_t)(MELT-1)*RNN*BB, SMEM);
    }
    gbar();

    // ================= epilogue: mel + gate projection =================
    for (int u = blk; u < MELT*2; u += NBLK) {
        int t = u >> 1, rz = u & 1;
        const int rp2 = (tid >> 4) << 1, bp = (tid & 15) << 1;
        const int rg0 = rz*64 + rp2, rg1 = rg0 + 1;
        float bv0 = (rg0 < NMEL) ? projB[rg0] : ((rg0 == NMEL) ? gateB[0] : 0.f);
        float bv1 = (rg1 < NMEL) ? projB[rg1] : ((rg1 == NMEL) ? gateB[0] : 0.f);
        float2 A0 = make_float2(bv0, bv0);
        float2 A1 = make_float2(bv1, bv1);
        gemm64c(A0, A1, g_projT + (size_t)rz*1536*64,
                g_dhh + (size_t)t*RNN*BB, RNN, SMEM);
        gemm64c(A0, A1, g_projT + ((size_t)rz*1536 + RNN)*64,
                g_ctxh + (size_t)t*ENC*BB, ENC, SMEM);
        if (rg0 < NMEL) {
            out[((size_t)(bp + 0)*NMEL + rg0)*MELT + t] = A0.x;
            out[((size_t)(bp + 1)*NMEL + rg0)*MELT + t] = A0.y;
        } else if (rg0 == NMEL) {
            out[GATE_OFF + (size_t)(bp + 0)*MELT + t] = A0.x;
            out[GATE_OFF + (size_t)(bp + 1)*MELT + t] = A0.y;
        }
        if (rg1 < NMEL) {
            out[((size_t)(bp + 0)*NMEL + rg1)*MELT + t] = A1.x;
            out[((size_t)(bp + 1)*NMEL + rg1)*MELT + t] = A1.y;
        } else if (rg1 == NMEL) {
            out[GATE_OFF + (size_t)(bp + 0)*MELT + t] = A1.x;
            out[GATE_OFF + (size_t)(bp + 1)*MELT + t] = A1.y;
        }
        __syncthreads();
    }
}

extern "C" void kernel_launch(void* const* d_in, const int* in_sizes, int n_in,
                              void* d_out, int out_size)
{
    decoder_all<<<NBLK, NTHR>>>(
        (const float*)d_in[0],  (const float*)d_in[1],  (const int*)d_in[2],
        (const float*)d_in[3],  (const float*)d_in[4],
        (const float*)d_in[5],  (const float*)d_in[6],  (const float*)d_in[7],
        (const float*)d_in[8],  (const float*)d_in[9],  (const float*)d_in[10],
        (const float*)d_in[11], (const float*)d_in[12],
        (const float*)d_in[13], (const float*)d_in[14], (const float*)d_in[15],
        (const float*)d_in[16], (const float*)d_in[17],
        (const float*)d_in[18], (const float*)d_in[19],
        (float*)d_out);
}